// round 1
// baseline (speedup 1.0000x reference)
#include <cuda_runtime.h>
#include <math.h>

#define DIMN 2048
#define NH 16
#define HD 128
#define MEMN 128
#define SEQN 2048
#define BATCH 4
#define HID 5632
#define NCHUNK (SEQN / MEMN)     // 16
#define RROWS (BATCH * MEMN)     // 512 rows per step
#define TOTAL (2 * MEMN)         // 256
#define EPS 1e-5f

// ---------------- scratch (__device__ globals; no allocation) ----------------
__device__ float g_om [RROWS * DIMN];
__device__ float g_sx [RROWS * DIMN];
__device__ float g_om2[RROWS * DIMN];
__device__ float g_h  [RROWS * DIMN];   // reused for FFN output f
__device__ float g_g1 [RROWS * HID];
__device__ float g_g3 [RROWS * HID];
__device__ float g_om4[RROWS * DIMN];
__device__ float g_mk [RROWS * DIMN];
__device__ float g_mv [RROWS * DIMN];
__device__ float g_xq [RROWS * DIMN];
__device__ float g_xk [RROWS * DIMN];
__device__ float g_xv [RROWS * DIMN];
__device__ float g_q  [BATCH * NH * MEMN  * HD];   // roped queries (x part only)
__device__ float g_k  [BATCH * NH * TOTAL * HD];
__device__ float g_v  [BATCH * NH * TOTAL * HD];
__device__ float g_s  [BATCH * NH * MEMN * TOTAL]; // scores / probs
__device__ float g_y  [BATCH * SEQN * DIMN];       // per-chunk outputs == om chain

// ---------------- reductions ----------------
__device__ __forceinline__ float block_sum256(float v) {
    __shared__ float sh[8];
    #pragma unroll
    for (int o = 16; o > 0; o >>= 1) v += __shfl_xor_sync(0xffffffffu, v, o);
    if ((threadIdx.x & 31) == 0) sh[threadIdx.x >> 5] = v;
    __syncthreads();
    float t = 0.f;
    if (threadIdx.x < 32) {
        t = (threadIdx.x < 8) ? sh[threadIdx.x] : 0.f;
        #pragma unroll
        for (int o = 4; o > 0; o >>= 1) t += __shfl_xor_sync(0xffffffffu, t, o);
        if (threadIdx.x == 0) sh[0] = t;
    }
    __syncthreads();
    float r = sh[0];
    __syncthreads();
    return r;
}

__device__ __forceinline__ float block_max256(float v) {
    __shared__ float sh[8];
    #pragma unroll
    for (int o = 16; o > 0; o >>= 1) v = fmaxf(v, __shfl_xor_sync(0xffffffffu, v, o));
    if ((threadIdx.x & 31) == 0) sh[threadIdx.x >> 5] = v;
    __syncthreads();
    float t = -3.4e38f;
    if (threadIdx.x < 32) {
        t = (threadIdx.x < 8) ? sh[threadIdx.x] : -3.4e38f;
        #pragma unroll
        for (int o = 4; o > 0; o >>= 1) t = fmaxf(t, __shfl_xor_sync(0xffffffffu, t, o));
        if (threadIdx.x == 0) sh[0] = t;
    }
    __syncthreads();
    float r = sh[0];
    __syncthreads();
    return r;
}

// ---------------- generic SIMT GEMM: C[M,N] = A[M,K] @ B[K,N], row-major ----
// BM=BN=64, BK=16, 256 threads, 4x4 micro-tile. Requires M%64==N%64==K%16==0.
__global__ void __launch_bounds__(256) gemm_nn64(
    const float* __restrict__ A, const float* __restrict__ B,
    float* __restrict__ C, int M, int N, int K)
{
    __shared__ float As[16][64];   // [k][m]
    __shared__ float Bs[16][64];   // [k][n]
    int tid = threadIdx.x;
    int tx = tid & 15, ty = tid >> 4;
    int row0 = blockIdx.y * 64, col0 = blockIdx.x * 64;
    int arow = tid >> 2;            // 0..63
    int acol = (tid & 3) * 4;       // 0,4,8,12
    int brow = tid >> 4;            // 0..15
    int bcol = (tid & 15) * 4;      // 0..60

    float acc[4][4] = {};

    for (int kk = 0; kk < K; kk += 16) {
        float4 av = *(const float4*)&A[(size_t)(row0 + arow) * K + kk + acol];
        As[acol + 0][arow] = av.x;
        As[acol + 1][arow] = av.y;
        As[acol + 2][arow] = av.z;
        As[acol + 3][arow] = av.w;
        float4 bv = *(const float4*)&B[(size_t)(kk + brow) * N + col0 + bcol];
        *(float4*)&Bs[brow][bcol] = bv;
        __syncthreads();
        #pragma unroll
        for (int k = 0; k < 16; k++) {
            float4 a = *(const float4*)&As[k][ty * 4];
            float4 b = *(const float4*)&Bs[k][tx * 4];
            float ar[4] = {a.x, a.y, a.z, a.w};
            float br[4] = {b.x, b.y, b.z, b.w};
            #pragma unroll
            for (int i = 0; i < 4; i++)
                #pragma unroll
                for (int j = 0; j < 4; j++)
                    acc[i][j] += ar[i] * br[j];
        }
        __syncthreads();
    }
    #pragma unroll
    for (int i = 0; i < 4; i++) {
        float4 o = make_float4(acc[i][0], acc[i][1], acc[i][2], acc[i][3]);
        *(float4*)&C[(size_t)(row0 + ty * 4 + i) * N + col0 + tx * 4] = o;
    }
}

// ---------------- gather rows of a [B][SEQ][DIM] tensor chunk into [512][DIM]
__global__ void __launch_bounds__(256) gather_rows(
    float* __restrict__ dst, const float* __restrict__ src, int chunk)
{
    int row = blockIdx.x;                // 0..511
    int b = row >> 7, i = row & 127;
    const float4* s = (const float4*)&src[((size_t)b * SEQN + chunk * MEMN + i) * DIMN];
    float4* d = (float4*)&dst[(size_t)row * DIMN];
    #pragma unroll
    for (int t = 0; t < 2; t++) d[threadIdx.x + t * 256] = s[threadIdx.x + t * 256];
}

// ---------------- rmsnorm: out = in * rsqrt(mean(in^2)+eps) * w --------------
__global__ void __launch_bounds__(256) rmsnorm_kernel(
    float* __restrict__ out, const float* __restrict__ in, const float* __restrict__ w)
{
    int row = blockIdx.x;
    const float* xr = in + (size_t)row * DIMN;
    float vals[8];
    float ss = 0.f;
    #pragma unroll
    for (int t = 0; t < 8; t++) {
        float v = xr[threadIdx.x + t * 256];
        vals[t] = v; ss += v * v;
    }
    float tot = block_sum256(ss);
    float sc = rsqrtf(tot * (1.0f / DIMN) + EPS);
    #pragma unroll
    for (int t = 0; t < 8; t++)
        out[(size_t)row * DIMN + threadIdx.x + t * 256] =
            vals[t] * sc * w[threadIdx.x + t * 256];
}

// ---------------- out = rmsnorm(a + b) * w ----------------------------------
__global__ void __launch_bounds__(256) add_rmsnorm_kernel(
    float* __restrict__ out, const float* __restrict__ a,
    const float* __restrict__ b, const float* __restrict__ w)
{
    int row = blockIdx.x;
    const float* ar = a + (size_t)row * DIMN;
    const float* br = b + (size_t)row * DIMN;
    float vals[8];
    float ss = 0.f;
    #pragma unroll
    for (int t = 0; t < 8; t++) {
        float v = ar[threadIdx.x + t * 256] + br[threadIdx.x + t * 256];
        vals[t] = v; ss += v * v;
    }
    float tot = block_sum256(ss);
    float sc = rsqrtf(tot * (1.0f / DIMN) + EPS);
    #pragma unroll
    for (int t = 0; t < 8; t++)
        out[(size_t)row * DIMN + threadIdx.x + t * 256] =
            vals[t] * sc * w[threadIdx.x + t * 256];
}

// ---------------- g1 = silu(g1) * g3 (float4 elementwise) -------------------
__global__ void __launch_bounds__(256) silu_mul_kernel(
    float* __restrict__ a, const float* __restrict__ b)
{
    int idx = blockIdx.x * 256 + threadIdx.x;
    int n4 = RROWS * HID / 4;
    if (idx >= n4) return;
    float4 av = ((float4*)a)[idx];
    float4 bv = ((const float4*)b)[idx];
    av.x = av.x / (1.f + expf(-av.x)) * bv.x;
    av.y = av.y / (1.f + expf(-av.y)) * bv.y;
    av.z = av.z / (1.f + expf(-av.z)) * bv.z;
    av.w = av.w / (1.f + expf(-av.w)) * bv.w;
    ((float4*)a)[idx] = av;
}

// ---------------- build K,V (all 256 positions) with RoPE on K --------------
__global__ void __launch_bounds__(256) build_kv_kernel(
    const float* __restrict__ mk, const float* __restrict__ mv,
    const float* __restrict__ xk, const float* __restrict__ xv,
    const float* __restrict__ fc, const float* __restrict__ fs,
    float* __restrict__ k, float* __restrict__ v)
{
    int idx = blockIdx.x * 256 + threadIdx.x;   // B*TOTAL*NH*64 = 1048576
    if (idx >= BATCH * TOTAL * NH * (HD / 2)) return;
    int j   = idx & 63;
    int h   = (idx >> 6) & 15;
    int pos = (idx >> 10) & 255;
    int b   = idx >> 18;
    int col = h * HD + 2 * j;
    const float *sk, *sv;
    if (pos < MEMN) {
        size_t r = (size_t)(b * MEMN + pos) * DIMN + col;
        sk = mk + r; sv = mv + r;
    } else {
        size_t r = (size_t)(b * MEMN + pos - MEMN) * DIMN + col;
        sk = xk + r; sv = xv + r;
    }
    float c = fc[pos * 64 + j], s = fs[pos * 64 + j];
    float kr = sk[0], ki = sk[1];
    size_t o = ((size_t)(b * NH + h) * TOTAL + pos) * HD + 2 * j;
    k[o]     = kr * c - ki * s;
    k[o + 1] = kr * s + ki * c;
    v[o]     = sv[0];
    v[o + 1] = sv[1];
}

// ---------------- build Q (only x part, positions 128..255) with RoPE -------
__global__ void __launch_bounds__(256) build_q_kernel(
    const float* __restrict__ xq, const float* __restrict__ fc,
    const float* __restrict__ fs, float* __restrict__ q)
{
    int idx = blockIdx.x * 256 + threadIdx.x;   // B*MEM*NH*64 = 524288
    if (idx >= BATCH * MEMN * NH * (HD / 2)) return;
    int j = idx & 63;
    int h = (idx >> 6) & 15;
    int i = (idx >> 10) & 127;
    int b = idx >> 17;
    int pos = MEMN + i;
    const float* src = xq + (size_t)(b * MEMN + i) * DIMN + h * HD + 2 * j;
    float c = fc[pos * 64 + j], s = fs[pos * 64 + j];
    float r = src[0], im = src[1];
    size_t o = ((size_t)(b * NH + h) * MEMN + i) * HD + 2 * j;
    q[o]     = r * c - im * s;
    q[o + 1] = r * s + im * c;
}

// ---------------- S[bh][i][j] = scale * q[bh][i]·k[bh][j] -------------------
// grid (jt=4, it=2, bh=64), block 256
__global__ void __launch_bounds__(256) qk_kernel(
    const float* __restrict__ q, const float* __restrict__ k,
    float* __restrict__ s, float scale)
{
    __shared__ float Qs[64][64];   // [d][i]
    __shared__ float Ks[64][64];   // [d][j]
    int bh = blockIdx.z;
    int i0 = blockIdx.y * 64;
    int j0 = blockIdx.x * 64;
    int tid = threadIdx.x, tx = tid & 15, ty = tid >> 4;
    const float* qb = q + (size_t)bh * MEMN * HD;
    const float* kb = k + (size_t)bh * TOTAL * HD;
    float acc[4][4] = {};

    for (int dc = 0; dc < HD; dc += 64) {
        for (int t = tid; t < 64 * 16; t += 256) {
            int r = t >> 4;
            int c4 = (t & 15) * 4;
            float4 a = *(const float4*)&qb[(size_t)(i0 + r) * HD + dc + c4];
            Qs[c4 + 0][r] = a.x; Qs[c4 + 1][r] = a.y;
            Qs[c4 + 2][r] = a.z; Qs[c4 + 3][r] = a.w;
            float4 b = *(const float4*)&kb[(size_t)(j0 + r) * HD + dc + c4];
            Ks[c4 + 0][r] = b.x; Ks[c4 + 1][r] = b.y;
            Ks[c4 + 2][r] = b.z; Ks[c4 + 3][r] = b.w;
        }
        __syncthreads();
        #pragma unroll
        for (int d = 0; d < 64; d++) {
            float4 a = *(const float4*)&Qs[d][ty * 4];
            float4 b = *(const float4*)&Ks[d][tx * 4];
            float ar[4] = {a.x, a.y, a.z, a.w};
            float br[4] = {b.x, b.y, b.z, b.w};
            #pragma unroll
            for (int i = 0; i < 4; i++)
                #pragma unroll
                for (int j = 0; j < 4; j++)
                    acc[i][j] += ar[i] * br[j];
        }
        __syncthreads();
    }
    #pragma unroll
    for (int i = 0; i < 4; i++) {
        float4 o = make_float4(acc[i][0] * scale, acc[i][1] * scale,
                               acc[i][2] * scale, acc[i][3] * scale);
        *(float4*)&s[((size_t)bh * MEMN + i0 + ty * 4 + i) * TOTAL + j0 + tx * 4] = o;
    }
}

// ---------------- causal softmax over rows of S (query pos = MEM + i) -------
__global__ void __launch_bounds__(256) softmax_kernel(float* __restrict__ s)
{
    int bh = blockIdx.x >> 7;
    int i  = blockIdx.x & 127;
    float* row = s + ((size_t)bh * MEMN + i) * TOTAL;
    int tid = threadIdx.x;
    int limit = MEMN + i;           // valid keys j <= limit
    bool valid = (tid <= limit);
    float v = valid ? row[tid] : -3.4e38f;
    float m = block_max256(v);
    float e = valid ? expf(v - m) : 0.f;
    float sum = block_sum256(e);
    row[tid] = e / sum;
}

// ---------------- O = P@V, written straight into y chunk --------------------
// grid (it=2, bh=64), block 256: 64x128 output tile, 4x8 per thread
__global__ void __launch_bounds__(256) pv_kernel(
    const float* __restrict__ p, const float* __restrict__ v,
    float* __restrict__ y, int chunk)
{
    __shared__ float Ps[32][64];    // [j][i]
    __shared__ float Vs[32][128];   // [j][d]
    int bh = blockIdx.y;
    int i0 = blockIdx.x * 64;
    int b = bh >> 4, h = bh & 15;
    int tid = threadIdx.x, tx = tid & 15, ty = tid >> 4;
    const float* pb = p + (size_t)bh * MEMN * TOTAL;
    const float* vb = v + (size_t)bh * TOTAL * HD;
    float acc[4][8] = {};

    for (int j0 = 0; j0 < TOTAL; j0 += 32) {
        for (int t = tid; t < 64 * 8; t += 256) {
            int r = t >> 3;
            int c4 = (t & 7) * 4;
            float4 a = *(const float4*)&pb[(size_t)(i0 + r) * TOTAL + j0 + c4];
            Ps[c4 + 0][r] = a.x; Ps[c4 + 1][r] = a.y;
            Ps[c4 + 2][r] = a.z; Ps[c4 + 3][r] = a.w;
        }
        for (int t = tid; t < 32 * 32; t += 256) {
            int r = t >> 5;
            int c4 = (t & 31) * 4;
            *(float4*)&Vs[r][c4] = *(const float4*)&vb[(size_t)(j0 + r) * HD + c4];
        }
        __syncthreads();
        #pragma unroll
        for (int j = 0; j < 32; j++) {
            float4 a = *(const float4*)&Ps[j][ty * 4];
            float ar[4] = {a.x, a.y, a.z, a.w};
            float4 b0 = *(const float4*)&Vs[j][tx * 8];
            float4 b1 = *(const float4*)&Vs[j][tx * 8 + 4];
            float br[8] = {b0.x, b0.y, b0.z, b0.w, b1.x, b1.y, b1.z, b1.w};
            #pragma unroll
            for (int i = 0; i < 4; i++)
                #pragma unroll
                for (int jc = 0; jc < 8; jc++)
                    acc[i][jc] += ar[i] * br[jc];
        }
        __syncthreads();
    }
    #pragma unroll
    for (int i = 0; i < 4; i++) {
        size_t row = (size_t)b * SEQN + (size_t)chunk * MEMN + i0 + ty * 4 + i;
        float4 o0 = make_float4(acc[i][0], acc[i][1], acc[i][2], acc[i][3]);
        float4 o1 = make_float4(acc[i][4], acc[i][5], acc[i][6], acc[i][7]);
        *(float4*)&y[row * DIMN + h * HD + tx * 8]     = o0;
        *(float4*)&y[row * DIMN + h * HD + tx * 8 + 4] = o1;
    }
}

// ---------------- host orchestration ----------------------------------------
static void launch_gemm(const float* A, const float* B, float* C, int M, int N, int K)
{
    dim3 grid(N / 64, M / 64);
    gemm_nn64<<<grid, 256>>>(A, B, C, M, N, K);
}

extern "C" void kernel_launch(void* const* d_in, const int* in_sizes, int n_in,
                              void* d_out, int out_size)
{
    (void)in_sizes; (void)n_in; (void)out_size;
    const float* x   = (const float*)d_in[0];
    const float* fc  = (const float*)d_in[1];
    const float* fs  = (const float*)d_in[2];
    const float* om0 = (const float*)d_in[3];
    const float* wq  = (const float*)d_in[4];
    const float* wk  = (const float*)d_in[5];
    const float* wv  = (const float*)d_in[6];
    const float* wo  = (const float*)d_in[7];
    /* d_in[8] = wqm: unused (mq = mk and mq rows are never queried) */
    const float* wkm = (const float*)d_in[9];
    const float* wvm = (const float*)d_in[10];
    const float* wm  = (const float*)d_in[11];
    const float* ffw = (const float*)d_in[12];
    const float* w1  = (const float*)d_in[13];
    const float* w2  = (const float*)d_in[14];
    const float* w3  = (const float*)d_in[15];
    const float* mnw = (const float*)d_in[16];
    float* out = (float*)d_out;

    float *om, *sx, *om2, *h, *g1, *g3, *om4, *mk, *mv, *xq, *xk, *xv;
    float *q, *k, *v, *s, *y;
    cudaGetSymbolAddress((void**)&om,  g_om);
    cudaGetSymbolAddress((void**)&sx,  g_sx);
    cudaGetSymbolAddress((void**)&om2, g_om2);
    cudaGetSymbolAddress((void**)&h,   g_h);
    cudaGetSymbolAddress((void**)&g1,  g_g1);
    cudaGetSymbolAddress((void**)&g3,  g_g3);
    cudaGetSymbolAddress((void**)&om4, g_om4);
    cudaGetSymbolAddress((void**)&mk,  g_mk);
    cudaGetSymbolAddress((void**)&mv,  g_mv);
    cudaGetSymbolAddress((void**)&xq,  g_xq);
    cudaGetSymbolAddress((void**)&xk,  g_xk);
    cudaGetSymbolAddress((void**)&xv,  g_xv);
    cudaGetSymbolAddress((void**)&q,   g_q);
    cudaGetSymbolAddress((void**)&k,   g_k);
    cudaGetSymbolAddress((void**)&v,   g_v);
    cudaGetSymbolAddress((void**)&s,   g_s);
    cudaGetSymbolAddress((void**)&y,   g_y);

    const float scale = 0.08838834764831845f;   // 1/sqrt(128)

    for (int c = 0; c < NCHUNK; c++) {
        const float* omp;
        if (c == 0) {
            omp = om0;                           // origin_mem is contiguous [512][DIM]
        } else {
            gather_rows<<<RROWS, 256>>>(om, y, c - 1);
            omp = om;
        }
        gather_rows<<<RROWS, 256>>>(sx, x, c);

        // memory-stream FFN block
        launch_gemm(omp, wm, om2, RROWS, DIMN, DIMN);
        rmsnorm_kernel<<<RROWS, 256>>>(h, om2, ffw);
        launch_gemm(h, w1, g1, RROWS, HID, DIMN);
        launch_gemm(h, w3, g3, RROWS, HID, DIMN);
        silu_mul_kernel<<<(RROWS * HID / 4 + 255) / 256, 256>>>(g1, g3);
        launch_gemm(g1, w2, h, RROWS, DIMN, HID);          // f -> h (h dead now)
        add_rmsnorm_kernel<<<RROWS, 256>>>(om4, om2, h, mnw);

        // projections
        launch_gemm(om4, wkm, mk, RROWS, DIMN, DIMN);
        launch_gemm(om4, wvm, mv, RROWS, DIMN, DIMN);
        launch_gemm(sx,  wq,  xq, RROWS, DIMN, DIMN);
        launch_gemm(sx,  wk,  xk, RROWS, DIMN, DIMN);
        launch_gemm(sx,  wv,  xv, RROWS, DIMN, DIMN);

        // assemble roped q/k/v
        build_kv_kernel<<<(BATCH * TOTAL * NH * 64 + 255) / 256, 256>>>(
            mk, mv, xk, xv, fc, fs, k, v);
        build_q_kernel<<<(BATCH * MEMN * NH * 64 + 255) / 256, 256>>>(xq, fc, fs, q);

        // attention (only output rows MEM..2*MEM-1 are needed)
        {
            dim3 g(4, 2, BATCH * NH);
            qk_kernel<<<g, 256>>>(q, k, s, scale);
        }
        softmax_kernel<<<BATCH * NH * MEMN, 256>>>(s);
        {
            dim3 g(2, BATCH * NH);
            pv_kernel<<<g, 256>>>(s, v, y, c);
        }
    }

    // final projection: out = y @ wo
    launch_gemm(y, wo, out, BATCH * SEQN, DIMN, DIMN);
}

// round 5
// speedup vs baseline: 1.0443x; 1.0443x over previous
#include <cuda_runtime.h>
#include <math.h>

#define DIMN 2048
#define NH 16
#define HD 128
#define MEMN 128
#define SEQN 2048
#define BATCH 4
#define HID 5632
#define NCHUNK (SEQN / MEMN)     // 16
#define RROWS (BATCH * MEMN)     // 512 rows per step
#define TOTAL (2 * MEMN)         // 256
#define EPS 1e-5f

// ---------------- scratch (__device__ globals; no allocation) ----------------
__device__ float g_om [RROWS * DIMN];
__device__ float g_sx [RROWS * DIMN];
__device__ float g_om2[RROWS * DIMN];
__device__ float g_h  [RROWS * DIMN];   // reused for FFN output f
__device__ float g_g1 [RROWS * HID];
__device__ float g_g3 [RROWS * HID];
__device__ float g_om4[RROWS * DIMN];
__device__ float g_mk [RROWS * DIMN];
__device__ float g_mv [RROWS * DIMN];
__device__ float g_xq [RROWS * DIMN];
__device__ float g_xk [RROWS * DIMN];
__device__ float g_xv [RROWS * DIMN];
__device__ float g_q  [BATCH * NH * MEMN  * HD];   // roped queries (x part only)
__device__ float g_k  [BATCH * NH * TOTAL * HD];
__device__ float g_v  [BATCH * NH * TOTAL * HD];
__device__ float g_s  [BATCH * NH * MEMN * TOTAL]; // scores / probs
__device__ float g_y  [BATCH * SEQN * DIMN];       // per-chunk outputs == om chain

// ---------------- reductions ----------------
__device__ __forceinline__ float block_sum256(float v) {
    __shared__ float sh[8];
    #pragma unroll
    for (int o = 16; o > 0; o >>= 1) v += __shfl_xor_sync(0xffffffffu, v, o);
    if ((threadIdx.x & 31) == 0) sh[threadIdx.x >> 5] = v;
    __syncthreads();
    float t = 0.f;
    if (threadIdx.x < 32) {
        t = (threadIdx.x < 8) ? sh[threadIdx.x] : 0.f;
        #pragma unroll
        for (int o = 4; o > 0; o >>= 1) t += __shfl_xor_sync(0xffffffffu, t, o);
        if (threadIdx.x == 0) sh[0] = t;
    }
    __syncthreads();
    float r = sh[0];
    __syncthreads();
    return r;
}

__device__ __forceinline__ float block_max256(float v) {
    __shared__ float sh[8];
    #pragma unroll
    for (int o = 16; o > 0; o >>= 1) v = fmaxf(v, __shfl_xor_sync(0xffffffffu, v, o));
    if ((threadIdx.x & 31) == 0) sh[threadIdx.x >> 5] = v;
    __syncthreads();
    float t = -3.4e38f;
    if (threadIdx.x < 32) {
        t = (threadIdx.x < 8) ? sh[threadIdx.x] : -3.4e38f;
        #pragma unroll
        for (int o = 4; o > 0; o >>= 1) t = fmaxf(t, __shfl_xor_sync(0xffffffffu, t, o));
        if (threadIdx.x == 0) sh[0] = t;
    }
    __syncthreads();
    float r = sh[0];
    __syncthreads();
    return r;
}

// ---------------- tf32 helpers ----------------
__device__ __forceinline__ unsigned f2tf32(float f) {
    unsigned u;
    asm("cvt.rna.tf32.f32 %0, %1;" : "=r"(u) : "f"(f));
    return u;
}

// split f into hi (tf32) and lo (tf32 of residual)
__device__ __forceinline__ void split_tf32(float f, unsigned& hi, unsigned& lo) {
    hi = f2tf32(f);
    lo = f2tf32(f - __uint_as_float(hi));
}

__device__ __forceinline__ void mma_tf32(float c[4], const unsigned a[4], const unsigned b[2]) {
    asm volatile(
        "mma.sync.aligned.m16n8k8.row.col.f32.tf32.tf32.f32 "
        "{%0,%1,%2,%3}, {%4,%5,%6,%7}, {%8,%9}, {%0,%1,%2,%3};"
        : "+f"(c[0]), "+f"(c[1]), "+f"(c[2]), "+f"(c[3])
        : "r"(a[0]), "r"(a[1]), "r"(a[2]), "r"(a[3]), "r"(b[0]), "r"(b[1]));
}

// ---------------- 3xTF32 tensor-core GEMM: C = A @ B, row-major -------------
// BM=64, BN=128, BK=16, 256 threads (8 warps, 32x32 warp tiles).
// Split precision: c += Al*Bh + Ah*Bl + Ah*Bh  (error ~2^-22 per product).
// Static smem = 2*(64*20 + 16*136)*4 = 27648 B (under the 48KB static cap).
#define GBM 64
#define GBN 128
#define GBK 16
#define APAD 4    // (16+4)  % 32 == 20 -> stride 20 words; frag LDS conflict-light
#define BPAD 8    // (128+8) % 32 == 8  -> conflict-free B frag LDS

__global__ void __launch_bounds__(256) gemm_tf32x3(
    const float* __restrict__ A, const float* __restrict__ B,
    float* __restrict__ C, int M, int N, int K)
{
    __shared__ unsigned AsH[GBM][GBK + APAD];
    __shared__ unsigned AsL[GBM][GBK + APAD];
    __shared__ unsigned BsH[GBK][GBN + BPAD];
    __shared__ unsigned BsL[GBK][GBN + BPAD];

    const int tid  = threadIdx.x;
    const int lane = tid & 31;
    const int wid  = tid >> 5;
    const int warp_m = wid & 1;        // 2 warps along M
    const int warp_n = wid >> 1;       // 4 warps along N
    const int row0 = blockIdx.y * GBM;
    const int col0 = blockIdx.x * GBN;

    float acc[2][4][4];
    #pragma unroll
    for (int i = 0; i < 2; i++)
        #pragma unroll
        for (int j = 0; j < 4; j++)
            #pragma unroll
            for (int l = 0; l < 4; l++) acc[i][j][l] = 0.f;

    for (int kk = 0; kk < K; kk += GBK) {
        if (kk) __syncthreads();
        // load A tile (64x16): 256 float4, 1 per thread, coalesced
        {
            int m  = tid >> 2;          // 0..63
            int k4 = tid & 3;           // 0..3
            float4 v = *(const float4*)&A[(size_t)(row0 + m) * K + kk + k4 * 4];
            unsigned h0, l0, h1, l1, h2, l2, h3, l3;
            split_tf32(v.x, h0, l0);
            split_tf32(v.y, h1, l1);
            split_tf32(v.z, h2, l2);
            split_tf32(v.w, h3, l3);
            AsH[m][k4 * 4 + 0] = h0; AsL[m][k4 * 4 + 0] = l0;
            AsH[m][k4 * 4 + 1] = h1; AsL[m][k4 * 4 + 1] = l1;
            AsH[m][k4 * 4 + 2] = h2; AsL[m][k4 * 4 + 2] = l2;
            AsH[m][k4 * 4 + 3] = h3; AsL[m][k4 * 4 + 3] = l3;
        }
        // load B tile (16x128): 512 float4, 2 per thread, coalesced
        #pragma unroll
        for (int i = 0; i < 2; i++) {
            int idx = tid + i * 256;
            int kr = idx >> 5;          // 0..15
            int n4 = idx & 31;          // 0..31
            float4 v = *(const float4*)&B[(size_t)(kk + kr) * N + col0 + n4 * 4];
            unsigned h0, l0, h1, l1, h2, l2, h3, l3;
            split_tf32(v.x, h0, l0);
            split_tf32(v.y, h1, l1);
            split_tf32(v.z, h2, l2);
            split_tf32(v.w, h3, l3);
            BsH[kr][n4 * 4 + 0] = h0; BsL[kr][n4 * 4 + 0] = l0;
            BsH[kr][n4 * 4 + 1] = h1; BsL[kr][n4 * 4 + 1] = l1;
            BsH[kr][n4 * 4 + 2] = h2; BsL[kr][n4 * 4 + 2] = l2;
            BsH[kr][n4 * 4 + 3] = h3; BsL[kr][n4 * 4 + 3] = l3;
        }
        __syncthreads();

        #pragma unroll
        for (int ks = 0; ks < 2; ks++) {
            int kq = ks * 8 + (lane & 3);
            unsigned afH[2][4], afL[2][4];
            unsigned bfH[4][2], bfL[4][2];
            #pragma unroll
            for (int mf = 0; mf < 2; mf++) {
                int m = warp_m * 32 + mf * 16 + (lane >> 2);
                afH[mf][0] = AsH[m][kq];      afL[mf][0] = AsL[m][kq];
                afH[mf][1] = AsH[m + 8][kq];  afL[mf][1] = AsL[m + 8][kq];
                afH[mf][2] = AsH[m][kq + 4];  afL[mf][2] = AsL[m][kq + 4];
                afH[mf][3] = AsH[m + 8][kq + 4]; afL[mf][3] = AsL[m + 8][kq + 4];
            }
            #pragma unroll
            for (int nf = 0; nf < 4; nf++) {
                int n = warp_n * 32 + nf * 8 + (lane >> 2);
                bfH[nf][0] = BsH[kq][n];      bfL[nf][0] = BsL[kq][n];
                bfH[nf][1] = BsH[kq + 4][n];  bfL[nf][1] = BsL[kq + 4][n];
            }
            #pragma unroll
            for (int mf = 0; mf < 2; mf++)
                #pragma unroll
                for (int nf = 0; nf < 4; nf++) {
                    mma_tf32(acc[mf][nf], afL[mf], bfH[nf]);  // Al*Bh
                    mma_tf32(acc[mf][nf], afH[mf], bfL[nf]);  // Ah*Bl
                    mma_tf32(acc[mf][nf], afH[mf], bfH[nf]);  // Ah*Bh (largest last)
                }
        }
    }

    // epilogue
    #pragma unroll
    for (int mf = 0; mf < 2; mf++) {
        int row = row0 + warp_m * 32 + mf * 16 + (lane >> 2);
        #pragma unroll
        for (int nf = 0; nf < 4; nf++) {
            int col = col0 + warp_n * 32 + nf * 8 + 2 * (lane & 3);
            *(float2*)&C[(size_t)row * N + col] =
                make_float2(acc[mf][nf][0], acc[mf][nf][1]);
            *(float2*)&C[(size_t)(row + 8) * N + col] =
                make_float2(acc[mf][nf][2], acc[mf][nf][3]);
        }
    }
}

// ---------------- gather rows of a [B][SEQ][DIM] tensor chunk into [512][DIM]
__global__ void __launch_bounds__(256) gather_rows(
    float* __restrict__ dst, const float* __restrict__ src, int chunk)
{
    int row = blockIdx.x;                // 0..511
    int b = row >> 7, i = row & 127;
    const float4* s = (const float4*)&src[((size_t)b * SEQN + chunk * MEMN + i) * DIMN];
    float4* d = (float4*)&dst[(size_t)row * DIMN];
    #pragma unroll
    for (int t = 0; t < 2; t++) d[threadIdx.x + t * 256] = s[threadIdx.x + t * 256];
}

// ---------------- rmsnorm: out = in * rsqrt(mean(in^2)+eps) * w --------------
__global__ void __launch_bounds__(256) rmsnorm_kernel(
    float* __restrict__ out, const float* __restrict__ in, const float* __restrict__ w)
{
    int row = blockIdx.x;
    const float* xr = in + (size_t)row * DIMN;
    float vals[8];
    float ss = 0.f;
    #pragma unroll
    for (int t = 0; t < 8; t++) {
        float v = xr[threadIdx.x + t * 256];
        vals[t] = v; ss += v * v;
    }
    float tot = block_sum256(ss);
    float sc = rsqrtf(tot * (1.0f / DIMN) + EPS);
    #pragma unroll
    for (int t = 0; t < 8; t++)
        out[(size_t)row * DIMN + threadIdx.x + t * 256] =
            vals[t] * sc * w[threadIdx.x + t * 256];
}

// ---------------- out = rmsnorm(a + b) * w ----------------------------------
__global__ void __launch_bounds__(256) add_rmsnorm_kernel(
    float* __restrict__ out, const float* __restrict__ a,
    const float* __restrict__ b, const float* __restrict__ w)
{
    int row = blockIdx.x;
    const float* ar = a + (size_t)row * DIMN;
    const float* br = b + (size_t)row * DIMN;
    float vals[8];
    float ss = 0.f;
    #pragma unroll
    for (int t = 0; t < 8; t++) {
        float v = ar[threadIdx.x + t * 256] + br[threadIdx.x + t * 256];
        vals[t] = v; ss += v * v;
    }
    float tot = block_sum256(ss);
    float sc = rsqrtf(tot * (1.0f / DIMN) + EPS);
    #pragma unroll
    for (int t = 0; t < 8; t++)
        out[(size_t)row * DIMN + threadIdx.x + t * 256] =
            vals[t] * sc * w[threadIdx.x + t * 256];
}

// ---------------- g1 = silu(g1) * g3 (float4 elementwise) -------------------
__global__ void __launch_bounds__(256) silu_mul_kernel(
    float* __restrict__ a, const float* __restrict__ b)
{
    int idx = blockIdx.x * 256 + threadIdx.x;
    int n4 = RROWS * HID / 4;
    if (idx >= n4) return;
    float4 av = ((float4*)a)[idx];
    float4 bv = ((const float4*)b)[idx];
    av.x = av.x / (1.f + expf(-av.x)) * bv.x;
    av.y = av.y / (1.f + expf(-av.y)) * bv.y;
    av.z = av.z / (1.f + expf(-av.z)) * bv.z;
    av.w = av.w / (1.f + expf(-av.w)) * bv.w;
    ((float4*)a)[idx] = av;
}

// ---------------- build K,V (all 256 positions) with RoPE on K --------------
__global__ void __launch_bounds__(256) build_kv_kernel(
    const float* __restrict__ mk, const float* __restrict__ mv,
    const float* __restrict__ xk, const float* __restrict__ xv,
    const float* __restrict__ fc, const float* __restrict__ fs,
    float* __restrict__ k, float* __restrict__ v)
{
    int idx = blockIdx.x * 256 + threadIdx.x;   // B*TOTAL*NH*64 = 1048576
    if (idx >= BATCH * TOTAL * NH * (HD / 2)) return;
    int j   = idx & 63;
    int h   = (idx >> 6) & 15;
    int pos = (idx >> 10) & 255;
    int b   = idx >> 18;
    int col = h * HD + 2 * j;
    const float *sk, *sv;
    if (pos < MEMN) {
        size_t r = (size_t)(b * MEMN + pos) * DIMN + col;
        sk = mk + r; sv = mv + r;
    } else {
        size_t r = (size_t)(b * MEMN + pos - MEMN) * DIMN + col;
        sk = xk + r; sv = xv + r;
    }
    float c = fc[pos * 64 + j], s = fs[pos * 64 + j];
    float kr = sk[0], ki = sk[1];
    size_t o = ((size_t)(b * NH + h) * TOTAL + pos) * HD + 2 * j;
    k[o]     = kr * c - ki * s;
    k[o + 1] = kr * s + ki * c;
    v[o]     = sv[0];
    v[o + 1] = sv[1];
}

// ---------------- build Q (only x part, positions 128..255) with RoPE -------
__global__ void __launch_bounds__(256) build_q_kernel(
    const float* __restrict__ xq, const float* __restrict__ fc,
    const float* __restrict__ fs, float* __restrict__ q)
{
    int idx = blockIdx.x * 256 + threadIdx.x;   // B*MEM*NH*64 = 524288
    if (idx >= BATCH * MEMN * NH * (HD / 2)) return;
    int j = idx & 63;
    int h = (idx >> 6) & 15;
    int i = (idx >> 10) & 127;
    int b = idx >> 17;
    int pos = MEMN + i;
    const float* src = xq + (size_t)(b * MEMN + i) * DIMN + h * HD + 2 * j;
    float c = fc[pos * 64 + j], s = fs[pos * 64 + j];
    float r = src[0], im = src[1];
    size_t o = ((size_t)(b * NH + h) * MEMN + i) * HD + 2 * j;
    q[o]     = r * c - im * s;
    q[o + 1] = r * s + im * c;
}

// ---------------- S[bh][i][j] = scale * q[bh][i]·k[bh][j] -------------------
// grid (jt=4, it=2, bh=64), block 256
__global__ void __launch_bounds__(256) qk_kernel(
    const float* __restrict__ q, const float* __restrict__ k,
    float* __restrict__ s, float scale)
{
    __shared__ float Qs[64][64];   // [d][i]
    __shared__ float Ks[64][64];   // [d][j]
    int bh = blockIdx.z;
    int i0 = blockIdx.y * 64;
    int j0 = blockIdx.x * 64;
    int tid = threadIdx.x, tx = tid & 15, ty = tid >> 4;
    const float* qb = q + (size_t)bh * MEMN * HD;
    const float* kb = k + (size_t)bh * TOTAL * HD;
    float acc[4][4] = {};

    for (int dc = 0; dc < HD; dc += 64) {
        for (int t = tid; t < 64 * 16; t += 256) {
            int r = t >> 4;
            int c4 = (t & 15) * 4;
            float4 a = *(const float4*)&qb[(size_t)(i0 + r) * HD + dc + c4];
            Qs[c4 + 0][r] = a.x; Qs[c4 + 1][r] = a.y;
            Qs[c4 + 2][r] = a.z; Qs[c4 + 3][r] = a.w;
            float4 b = *(const float4*)&kb[(size_t)(j0 + r) * HD + dc + c4];
            Ks[c4 + 0][r] = b.x; Ks[c4 + 1][r] = b.y;
            Ks[c4 + 2][r] = b.z; Ks[c4 + 3][r] = b.w;
        }
        __syncthreads();
        #pragma unroll
        for (int d = 0; d < 64; d++) {
            float4 a = *(const float4*)&Qs[d][ty * 4];
            float4 b = *(const float4*)&Ks[d][tx * 4];
            float ar[4] = {a.x, a.y, a.z, a.w};
            float br[4] = {b.x, b.y, b.z, b.w};
            #pragma unroll
            for (int i = 0; i < 4; i++)
                #pragma unroll
                for (int j = 0; j < 4; j++)
                    acc[i][j] += ar[i] * br[j];
        }
        __syncthreads();
    }
    #pragma unroll
    for (int i = 0; i < 4; i++) {
        float4 o = make_float4(acc[i][0] * scale, acc[i][1] * scale,
                               acc[i][2] * scale, acc[i][3] * scale);
        *(float4*)&s[((size_t)bh * MEMN + i0 + ty * 4 + i) * TOTAL + j0 + tx * 4] = o;
    }
}

// ---------------- causal softmax over rows of S (query pos = MEM + i) -------
__global__ void __launch_bounds__(256) softmax_kernel(float* __restrict__ s)
{
    int bh = blockIdx.x >> 7;
    int i  = blockIdx.x & 127;
    float* row = s + ((size_t)bh * MEMN + i) * TOTAL;
    int tid = threadIdx.x;
    int limit = MEMN + i;           // valid keys j <= limit
    bool valid = (tid <= limit);
    float v = valid ? row[tid] : -3.4e38f;
    float m = block_max256(v);
    float e = valid ? expf(v - m) : 0.f;
    float sum = block_sum256(e);
    row[tid] = e / sum;
}

// ---------------- O = P@V, written straight into y chunk --------------------
// grid (it=2, bh=64), block 256: 64x128 output tile, 4x8 per thread
__global__ void __launch_bounds__(256) pv_kernel(
    const float* __restrict__ p, const float* __restrict__ v,
    float* __restrict__ y, int chunk)
{
    __shared__ float Ps[32][64];    // [j][i]
    __shared__ float Vs[32][128];   // [j][d]
    int bh = blockIdx.y;
    int i0 = blockIdx.x * 64;
    int b = bh >> 4, h = bh & 15;
    int tid = threadIdx.x, tx = tid & 15, ty = tid >> 4;
    const float* pb = p + (size_t)bh * MEMN * TOTAL;
    const float* vb = v + (size_t)bh * TOTAL * HD;
    float acc[4][8] = {};

    for (int j0 = 0; j0 < TOTAL; j0 += 32) {
        for (int t = tid; t < 64 * 8; t += 256) {
            int r = t >> 3;
            int c4 = (t & 7) * 4;
            float4 a = *(const float4*)&pb[(size_t)(i0 + r) * TOTAL + j0 + c4];
            Ps[c4 + 0][r] = a.x; Ps[c4 + 1][r] = a.y;
            Ps[c4 + 2][r] = a.z; Ps[c4 + 3][r] = a.w;
        }
        for (int t = tid; t < 32 * 32; t += 256) {
            int r = t >> 5;
            int c4 = (t & 31) * 4;
            *(float4*)&Vs[r][c4] = *(const float4*)&vb[(size_t)(j0 + r) * HD + c4];
        }
        __syncthreads();
        #pragma unroll
        for (int j = 0; j < 32; j++) {
            float4 a = *(const float4*)&Ps[j][ty * 4];
            float ar[4] = {a.x, a.y, a.z, a.w};
            float4 b0 = *(const float4*)&Vs[j][tx * 8];
            float4 b1 = *(const float4*)&Vs[j][tx * 8 + 4];
            float br[8] = {b0.x, b0.y, b0.z, b0.w, b1.x, b1.y, b1.z, b1.w};
            #pragma unroll
            for (int i = 0; i < 4; i++)
                #pragma unroll
                for (int jc = 0; jc < 8; jc++)
                    acc[i][jc] += ar[i] * br[jc];
        }
        __syncthreads();
    }
    #pragma unroll
    for (int i = 0; i < 4; i++) {
        size_t row = (size_t)b * SEQN + (size_t)chunk * MEMN + i0 + ty * 4 + i;
        float4 o0 = make_float4(acc[i][0], acc[i][1], acc[i][2], acc[i][3]);
        float4 o1 = make_float4(acc[i][4], acc[i][5], acc[i][6], acc[i][7]);
        *(float4*)&y[row * DIMN + h * HD + tx * 8]     = o0;
        *(float4*)&y[row * DIMN + h * HD + tx * 8 + 4] = o1;
    }
}

// ---------------- host orchestration ----------------------------------------
static void launch_gemm(const float* A, const float* B, float* C, int M, int N, int K)
{
    dim3 grid(N / GBN, M / GBM);
    gemm_tf32x3<<<grid, 256>>>(A, B, C, M, N, K);
}

extern "C" void kernel_launch(void* const* d_in, const int* in_sizes, int n_in,
                              void* d_out, int out_size)
{
    (void)in_sizes; (void)n_in; (void)out_size;
    const float* x   = (const float*)d_in[0];
    const float* fc  = (const float*)d_in[1];
    const float* fs  = (const float*)d_in[2];
    const float* om0 = (const float*)d_in[3];
    const float* wq  = (const float*)d_in[4];
    const float* wk  = (const float*)d_in[5];
    const float* wv  = (const float*)d_in[6];
    const float* wo  = (const float*)d_in[7];
    /* d_in[8] = wqm: unused (mq = mk and mq rows are never queried) */
    const float* wkm = (const float*)d_in[9];
    const float* wvm = (const float*)d_in[10];
    const float* wm  = (const float*)d_in[11];
    const float* ffw = (const float*)d_in[12];
    const float* w1  = (const float*)d_in[13];
    const float* w2  = (const float*)d_in[14];
    const float* w3  = (const float*)d_in[15];
    const float* mnw = (const float*)d_in[16];
    float* out = (float*)d_out;

    float *om, *sx, *om2, *h, *g1, *g3, *om4, *mk, *mv, *xq, *xk, *xv;
    float *q, *k, *v, *s, *y;
    cudaGetSymbolAddress((void**)&om,  g_om);
    cudaGetSymbolAddress((void**)&sx,  g_sx);
    cudaGetSymbolAddress((void**)&om2, g_om2);
    cudaGetSymbolAddress((void**)&h,   g_h);
    cudaGetSymbolAddress((void**)&g1,  g_g1);
    cudaGetSymbolAddress((void**)&g3,  g_g3);
    cudaGetSymbolAddress((void**)&om4, g_om4);
    cudaGetSymbolAddress((void**)&mk,  g_mk);
    cudaGetSymbolAddress((void**)&mv,  g_mv);
    cudaGetSymbolAddress((void**)&xq,  g_xq);
    cudaGetSymbolAddress((void**)&xk,  g_xk);
    cudaGetSymbolAddress((void**)&xv,  g_xv);
    cudaGetSymbolAddress((void**)&q,   g_q);
    cudaGetSymbolAddress((void**)&k,   g_k);
    cudaGetSymbolAddress((void**)&v,   g_v);
    cudaGetSymbolAddress((void**)&s,   g_s);
    cudaGetSymbolAddress((void**)&y,   g_y);

    const float scale = 0.08838834764831845f;   // 1/sqrt(128)

    for (int c = 0; c < NCHUNK; c++) {
        const float* omp;
        if (c == 0) {
            omp = om0;                           // origin_mem is contiguous [512][DIM]
        } else {
            gather_rows<<<RROWS, 256>>>(om, y, c - 1);
            omp = om;
        }
        gather_rows<<<RROWS, 256>>>(sx, x, c);

        // memory-stream FFN block
        launch_gemm(omp, wm, om2, RROWS, DIMN, DIMN);
        rmsnorm_kernel<<<RROWS, 256>>>(h, om2, ffw);
        launch_gemm(h, w1, g1, RROWS, HID, DIMN);
        launch_gemm(h, w3, g3, RROWS, HID, DIMN);
        silu_mul_kernel<<<(RROWS * HID / 4 + 255) / 256, 256>>>(g1, g3);
        launch_gemm(g1, w2, h, RROWS, DIMN, HID);          // f -> h (h dead now)
        add_rmsnorm_kernel<<<RROWS, 256>>>(om4, om2, h, mnw);

        // projections
        launch_gemm(om4, wkm, mk, RROWS, DIMN, DIMN);
        launch_gemm(om4, wvm, mv, RROWS, DIMN, DIMN);
        launch_gemm(sx,  wq,  xq, RROWS, DIMN, DIMN);
        launch_gemm(sx,  wk,  xk, RROWS, DIMN, DIMN);
        launch_gemm(sx,  wv,  xv, RROWS, DIMN, DIMN);

        // assemble roped q/k/v
        build_kv_kernel<<<(BATCH * TOTAL * NH * 64 + 255) / 256, 256>>>(
            mk, mv, xk, xv, fc, fs, k, v);
        build_q_kernel<<<(BATCH * MEMN * NH * 64 + 255) / 256, 256>>>(xq, fc, fs, q);

        // attention (only output rows MEM..2*MEM-1 are needed)
        {
            dim3 g(4, 2, BATCH * NH);
            qk_kernel<<<g, 256>>>(q, k, s, scale);
        }
        softmax_kernel<<<BATCH * NH * MEMN, 256>>>(s);
        {
            dim3 g(2, BATCH * NH);
            pv_kernel<<<g, 256>>>(s, v, y, c);
        }
    }

    // final projection: out = y @ wo
    launch_gemm(y, wo, out, BATCH * SEQN, DIMN, DIMN);
}

// round 7
// speedup vs baseline: 1.1957x; 1.1450x over previous
#include <cuda_runtime.h>
#include <math.h>

#define DIMN 2048
#define NH 16
#define HD 128
#define MEMN 128
#define SEQN 2048
#define BATCH 4
#define HID 5632
#define NCHUNK (SEQN / MEMN)     // 16
#define RROWS (BATCH * MEMN)     // 512 rows per step
#define TOTAL (2 * MEMN)         // 256
#define EPS 1e-5f

// ---------------- scratch (__device__ globals; no allocation) ----------------
__device__ float g_om [RROWS * DIMN];
__device__ float g_sx [RROWS * DIMN];
__device__ float g_om2[RROWS * DIMN];
__device__ float g_h  [RROWS * DIMN];   // reused for FFN output f
__device__ float g_g1 [RROWS * HID];
__device__ float g_g3 [RROWS * HID];
__device__ float g_om4[RROWS * DIMN];
__device__ float g_mk [RROWS * DIMN];
__device__ float g_mv [RROWS * DIMN];
__device__ float g_xq [RROWS * DIMN];
__device__ float g_xk [RROWS * DIMN];
__device__ float g_xv [RROWS * DIMN];
__device__ float g_q  [BATCH * NH * MEMN  * HD];   // roped queries (x part only)
__device__ float g_k  [BATCH * NH * TOTAL * HD];
__device__ float g_v  [BATCH * NH * TOTAL * HD];
__device__ float g_s  [BATCH * NH * MEMN * TOTAL]; // scores / probs
__device__ float g_y  [BATCH * SEQN * DIMN];       // per-chunk outputs == om chain

// ---------------- reductions ----------------
__device__ __forceinline__ float block_sum256(float v) {
    __shared__ float sh[8];
    #pragma unroll
    for (int o = 16; o > 0; o >>= 1) v += __shfl_xor_sync(0xffffffffu, v, o);
    if ((threadIdx.x & 31) == 0) sh[threadIdx.x >> 5] = v;
    __syncthreads();
    float t = 0.f;
    if (threadIdx.x < 32) {
        t = (threadIdx.x < 8) ? sh[threadIdx.x] : 0.f;
        #pragma unroll
        for (int o = 4; o > 0; o >>= 1) t += __shfl_xor_sync(0xffffffffu, t, o);
        if (threadIdx.x == 0) sh[0] = t;
    }
    __syncthreads();
    float r = sh[0];
    __syncthreads();
    return r;
}

__device__ __forceinline__ float block_max256(float v) {
    __shared__ float sh[8];
    #pragma unroll
    for (int o = 16; o > 0; o >>= 1) v = fmaxf(v, __shfl_xor_sync(0xffffffffu, v, o));
    if ((threadIdx.x & 31) == 0) sh[threadIdx.x >> 5] = v;
    __syncthreads();
    float t = -3.4e38f;
    if (threadIdx.x < 32) {
        t = (threadIdx.x < 8) ? sh[threadIdx.x] : -3.4e38f;
        #pragma unroll
        for (int o = 4; o > 0; o >>= 1) t = fmaxf(t, __shfl_xor_sync(0xffffffffu, t, o));
        if (threadIdx.x == 0) sh[0] = t;
    }
    __syncthreads();
    float r = sh[0];
    __syncthreads();
    return r;
}

// ---------------- tf32 helpers ----------------
__device__ __forceinline__ unsigned f2tf32(float f) {
    unsigned u;
    asm("cvt.rna.tf32.f32 %0, %1;" : "=r"(u) : "f"(f));
    return u;
}

// split f into hi (tf32) and lo (tf32 of residual)
__device__ __forceinline__ void split_tf32(float f, unsigned& hi, unsigned& lo) {
    hi = f2tf32(f);
    lo = f2tf32(f - __uint_as_float(hi));
}

__device__ __forceinline__ void mma_tf32(float c[4], const unsigned a[4], const unsigned b[2]) {
    asm volatile(
        "mma.sync.aligned.m16n8k8.row.col.f32.tf32.tf32.f32 "
        "{%0,%1,%2,%3}, {%4,%5,%6,%7}, {%8,%9}, {%0,%1,%2,%3};"
        : "+f"(c[0]), "+f"(c[1]), "+f"(c[2]), "+f"(c[3])
        : "r"(a[0]), "r"(a[1]), "r"(a[2]), "r"(a[3]), "r"(b[0]), "r"(b[1]));
}

// ---------------- 3xTF32 tensor-core GEMM: C = A @ B, row-major -------------
// BM=64, BN=128, BK=32, 256 threads (8 warps, 32x32 warp tiles).
// Register-prefetch double buffering: next tile's LDGs issue before compute;
// split+store happens after compute, so LDG latency hides under 96 MMAs.
// Static smem = (64*32 + 32*128)*2*4 = 49152 B exactly (the static cap).
// A is XOR-swizzled (col ^= (m&7)*4) -> conflict-free STS.128 and frag LDS.
// B needs no swizzle: stores lane-consecutive, frag reads 4-lane broadcast.
#define GBM 64
#define GBN 128
#define GBK 32

__global__ void __launch_bounds__(256) gemm_tf32x3(
    const float* __restrict__ A, const float* __restrict__ B,
    float* __restrict__ C, int M, int N, int K)
{
    __shared__ unsigned AsH[GBM][GBK];
    __shared__ unsigned AsL[GBM][GBK];
    __shared__ unsigned BsH[GBK][GBN];
    __shared__ unsigned BsL[GBK][GBN];

    const int tid  = threadIdx.x;
    const int lane = tid & 31;
    const int wid  = tid >> 5;
    const int warp_m = wid & 1;        // 2 warps along M
    const int warp_n = wid >> 1;       // 4 warps along N
    const int row0 = blockIdx.y * GBM;
    const int col0 = blockIdx.x * GBN;

    float4 ra[2];    // A tile 64x32 floats: 2 float4/thread
    float4 rb[4];    // B tile 32x128 floats: 4 float4/thread

    float acc[2][4][4];
    #pragma unroll
    for (int i = 0; i < 2; i++)
        #pragma unroll
        for (int j = 0; j < 4; j++)
            #pragma unroll
            for (int l = 0; l < 4; l++) acc[i][j][l] = 0.f;

    // ---- prologue: load tile 0 into registers ----
    #pragma unroll
    for (int i = 0; i < 2; i++) {
        int idx = tid + i * 256;
        int m = idx >> 3, k4 = idx & 7;
        ra[i] = *(const float4*)&A[(size_t)(row0 + m) * K + k4 * 4];
    }
    #pragma unroll
    for (int i = 0; i < 4; i++) {
        int idx = tid + i * 256;
        int kr = idx >> 5, n4 = idx & 31;
        rb[i] = *(const float4*)&B[(size_t)kr * N + col0 + n4 * 4];
    }

    for (int kk = 0; kk < K; kk += GBK) {
        // split + store the tile we just loaded into registers
        #pragma unroll
        for (int i = 0; i < 2; i++) {
            int idx = tid + i * 256;
            int m = idx >> 3, k4 = idx & 7;
            int kc = (k4 * 4) ^ ((m & 7) * 4);    // XOR swizzle (4-aligned)
            unsigned h0, l0, h1, l1, h2, l2, h3, l3;
            split_tf32(ra[i].x, h0, l0);
            split_tf32(ra[i].y, h1, l1);
            split_tf32(ra[i].z, h2, l2);
            split_tf32(ra[i].w, h3, l3);
            *(uint4*)&AsH[m][kc] = make_uint4(h0, h1, h2, h3);
            *(uint4*)&AsL[m][kc] = make_uint4(l0, l1, l2, l3);
        }
        #pragma unroll
        for (int i = 0; i < 4; i++) {
            int idx = tid + i * 256;
            int kr = idx >> 5, n4 = idx & 31;
            unsigned h0, l0, h1, l1, h2, l2, h3, l3;
            split_tf32(rb[i].x, h0, l0);
            split_tf32(rb[i].y, h1, l1);
            split_tf32(rb[i].z, h2, l2);
            split_tf32(rb[i].w, h3, l3);
            *(uint4*)&BsH[kr][n4 * 4] = make_uint4(h0, h1, h2, h3);
            *(uint4*)&BsL[kr][n4 * 4] = make_uint4(l0, l1, l2, l3);
        }
        __syncthreads();

        // prefetch next tile into registers (LDGs issue now, waited at next store)
        const bool more = (kk + GBK < K);
        if (more) {
            #pragma unroll
            for (int i = 0; i < 2; i++) {
                int idx = tid + i * 256;
                int m = idx >> 3, k4 = idx & 7;
                ra[i] = *(const float4*)&A[(size_t)(row0 + m) * K + kk + GBK + k4 * 4];
            }
            #pragma unroll
            for (int i = 0; i < 4; i++) {
                int idx = tid + i * 256;
                int kr = idx >> 5, n4 = idx & 31;
                rb[i] = *(const float4*)&B[(size_t)(kk + GBK + kr) * N + col0 + n4 * 4];
            }
        }

        // ---- compute: 4 k-slices x 24 MMAs ----
        #pragma unroll
        for (int ks = 0; ks < 4; ks++) {
            int kq = ks * 8 + (lane & 3);
            unsigned afH[2][4], afL[2][4];
            unsigned bfH[4][2], bfL[4][2];
            #pragma unroll
            for (int mf = 0; mf < 2; mf++) {
                int m  = warp_m * 32 + mf * 16 + (lane >> 2);
                int sw = (m & 7) * 4;               // (m+8) has same swizzle
                afH[mf][0] = AsH[m][kq ^ sw];
                afH[mf][1] = AsH[m + 8][kq ^ sw];
                afH[mf][2] = AsH[m][(kq + 4) ^ sw];
                afH[mf][3] = AsH[m + 8][(kq + 4) ^ sw];
                afL[mf][0] = AsL[m][kq ^ sw];
                afL[mf][1] = AsL[m + 8][kq ^ sw];
                afL[mf][2] = AsL[m][(kq + 4) ^ sw];
                afL[mf][3] = AsL[m + 8][(kq + 4) ^ sw];
            }
            #pragma unroll
            for (int nf = 0; nf < 4; nf++) {
                int n = warp_n * 32 + nf * 8 + (lane >> 2);
                bfH[nf][0] = BsH[kq][n];
                bfH[nf][1] = BsH[kq + 4][n];
                bfL[nf][0] = BsL[kq][n];
                bfL[nf][1] = BsL[kq + 4][n];
            }
            #pragma unroll
            for (int mf = 0; mf < 2; mf++)
                #pragma unroll
                for (int nf = 0; nf < 4; nf++) {
                    mma_tf32(acc[mf][nf], afL[mf], bfH[nf]);  // Al*Bh
                    mma_tf32(acc[mf][nf], afH[mf], bfL[nf]);  // Ah*Bl
                    mma_tf32(acc[mf][nf], afH[mf], bfH[nf]);  // Ah*Bh (largest last)
                }
        }
        __syncthreads();   // done reading smem; next iter overwrites
    }

    // epilogue
    #pragma unroll
    for (int mf = 0; mf < 2; mf++) {
        int row = row0 + warp_m * 32 + mf * 16 + (lane >> 2);
        #pragma unroll
        for (int nf = 0; nf < 4; nf++) {
            int col = col0 + warp_n * 32 + nf * 8 + 2 * (lane & 3);
            *(float2*)&C[(size_t)row * N + col] =
                make_float2(acc[mf][nf][0], acc[mf][nf][1]);
            *(float2*)&C[(size_t)(row + 8) * N + col] =
                make_float2(acc[mf][nf][2], acc[mf][nf][3]);
        }
    }
}

// ---------------- gather rows of a [B][SEQ][DIM] tensor chunk into [512][DIM]
__global__ void __launch_bounds__(256) gather_rows(
    float* __restrict__ dst, const float* __restrict__ src, int chunk)
{
    int row = blockIdx.x;                // 0..511
    int b = row >> 7, i = row & 127;
    const float4* s = (const float4*)&src[((size_t)b * SEQN + chunk * MEMN + i) * DIMN];
    float4* d = (float4*)&dst[(size_t)row * DIMN];
    #pragma unroll
    for (int t = 0; t < 2; t++) d[threadIdx.x + t * 256] = s[threadIdx.x + t * 256];
}

// ---------------- rmsnorm: out = in * rsqrt(mean(in^2)+eps) * w --------------
__global__ void __launch_bounds__(256) rmsnorm_kernel(
    float* __restrict__ out, const float* __restrict__ in, const float* __restrict__ w)
{
    int row = blockIdx.x;
    const float* xr = in + (size_t)row * DIMN;
    float vals[8];
    float ss = 0.f;
    #pragma unroll
    for (int t = 0; t < 8; t++) {
        float v = xr[threadIdx.x + t * 256];
        vals[t] = v; ss += v * v;
    }
    float tot = block_sum256(ss);
    float sc = rsqrtf(tot * (1.0f / DIMN) + EPS);
    #pragma unroll
    for (int t = 0; t < 8; t++)
        out[(size_t)row * DIMN + threadIdx.x + t * 256] =
            vals[t] * sc * w[threadIdx.x + t * 256];
}

// ---------------- out = rmsnorm(a + b) * w ----------------------------------
__global__ void __launch_bounds__(256) add_rmsnorm_kernel(
    float* __restrict__ out, const float* __restrict__ a,
    const float* __restrict__ b, const float* __restrict__ w)
{
    int row = blockIdx.x;
    const float* ar = a + (size_t)row * DIMN;
    const float* br = b + (size_t)row * DIMN;
    float vals[8];
    float ss = 0.f;
    #pragma unroll
    for (int t = 0; t < 8; t++) {
        float v = ar[threadIdx.x + t * 256] + br[threadIdx.x + t * 256];
        vals[t] = v; ss += v * v;
    }
    float tot = block_sum256(ss);
    float sc = rsqrtf(tot * (1.0f / DIMN) + EPS);
    #pragma unroll
    for (int t = 0; t < 8; t++)
        out[(size_t)row * DIMN + threadIdx.x + t * 256] =
            vals[t] * sc * w[threadIdx.x + t * 256];
}

// ---------------- g1 = silu(g1) * g3 (float4 elementwise) -------------------
__global__ void __launch_bounds__(256) silu_mul_kernel(
    float* __restrict__ a, const float* __restrict__ b)
{
    int idx = blockIdx.x * 256 + threadIdx.x;
    int n4 = RROWS * HID / 4;
    if (idx >= n4) return;
    float4 av = ((float4*)a)[idx];
    float4 bv = ((const float4*)b)[idx];
    av.x = av.x / (1.f + expf(-av.x)) * bv.x;
    av.y = av.y / (1.f + expf(-av.y)) * bv.y;
    av.z = av.z / (1.f + expf(-av.z)) * bv.z;
    av.w = av.w / (1.f + expf(-av.w)) * bv.w;
    ((float4*)a)[idx] = av;
}

// ---------------- build K,V (all 256 positions) with RoPE on K --------------
__global__ void __launch_bounds__(256) build_kv_kernel(
    const float* __restrict__ mk, const float* __restrict__ mv,
    const float* __restrict__ xk, const float* __restrict__ xv,
    const float* __restrict__ fc, const float* __restrict__ fs,
    float* __restrict__ k, float* __restrict__ v)
{
    int idx = blockIdx.x * 256 + threadIdx.x;   // B*TOTAL*NH*64 = 1048576
    if (idx >= BATCH * TOTAL * NH * (HD / 2)) return;
    int j   = idx & 63;
    int h   = (idx >> 6) & 15;
    int pos = (idx >> 10) & 255;
    int b   = idx >> 18;
    int col = h * HD + 2 * j;
    const float *sk, *sv;
    if (pos < MEMN) {
        size_t r = (size_t)(b * MEMN + pos) * DIMN + col;
        sk = mk + r; sv = mv + r;
    } else {
        size_t r = (size_t)(b * MEMN + pos - MEMN) * DIMN + col;
        sk = xk + r; sv = xv + r;
    }
    float c = fc[pos * 64 + j], s = fs[pos * 64 + j];
    float kr = sk[0], ki = sk[1];
    size_t o = ((size_t)(b * NH + h) * TOTAL + pos) * HD + 2 * j;
    k[o]     = kr * c - ki * s;
    k[o + 1] = kr * s + ki * c;
    v[o]     = sv[0];
    v[o + 1] = sv[1];
}

// ---------------- build Q (only x part, positions 128..255) with RoPE -------
__global__ void __launch_bounds__(256) build_q_kernel(
    const float* __restrict__ xq, const float* __restrict__ fc,
    const float* __restrict__ fs, float* __restrict__ q)
{
    int idx = blockIdx.x * 256 + threadIdx.x;   // B*MEM*NH*64 = 524288
    if (idx >= BATCH * MEMN * NH * (HD / 2)) return;
    int j = idx & 63;
    int h = (idx >> 6) & 15;
    int i = (idx >> 10) & 127;
    int b = idx >> 17;
    int pos = MEMN + i;
    const float* src = xq + (size_t)(b * MEMN + i) * DIMN + h * HD + 2 * j;
    float c = fc[pos * 64 + j], s = fs[pos * 64 + j];
    float r = src[0], im = src[1];
    size_t o = ((size_t)(b * NH + h) * MEMN + i) * HD + 2 * j;
    q[o]     = r * c - im * s;
    q[o + 1] = r * s + im * c;
}

// ---------------- S[bh][i][j] = scale * q[bh][i]·k[bh][j] -------------------
// grid (jt=4, it=2, bh=64), block 256
__global__ void __launch_bounds__(256) qk_kernel(
    const float* __restrict__ q, const float* __restrict__ k,
    float* __restrict__ s, float scale)
{
    __shared__ float Qs[64][64];   // [d][i]
    __shared__ float Ks[64][64];   // [d][j]
    int bh = blockIdx.z;
    int i0 = blockIdx.y * 64;
    int j0 = blockIdx.x * 64;
    int tid = threadIdx.x, tx = tid & 15, ty = tid >> 4;
    const float* qb = q + (size_t)bh * MEMN * HD;
    const float* kb = k + (size_t)bh * TOTAL * HD;
    float acc[4][4] = {};

    for (int dc = 0; dc < HD; dc += 64) {
        for (int t = tid; t < 64 * 16; t += 256) {
            int r = t >> 4;
            int c4 = (t & 15) * 4;
            float4 a = *(const float4*)&qb[(size_t)(i0 + r) * HD + dc + c4];
            Qs[c4 + 0][r] = a.x; Qs[c4 + 1][r] = a.y;
            Qs[c4 + 2][r] = a.z; Qs[c4 + 3][r] = a.w;
            float4 b = *(const float4*)&kb[(size_t)(j0 + r) * HD + dc + c4];
            Ks[c4 + 0][r] = b.x; Ks[c4 + 1][r] = b.y;
            Ks[c4 + 2][r] = b.z; Ks[c4 + 3][r] = b.w;
        }
        __syncthreads();
        #pragma unroll
        for (int d = 0; d < 64; d++) {
            float4 a = *(const float4*)&Qs[d][ty * 4];
            float4 b = *(const float4*)&Ks[d][tx * 4];
            float ar[4] = {a.x, a.y, a.z, a.w};
            float br[4] = {b.x, b.y, b.z, b.w};
            #pragma unroll
            for (int i = 0; i < 4; i++)
                #pragma unroll
                for (int j = 0; j < 4; j++)
                    acc[i][j] += ar[i] * br[j];
        }
        __syncthreads();
    }
    #pragma unroll
    for (int i = 0; i < 4; i++) {
        float4 o = make_float4(acc[i][0] * scale, acc[i][1] * scale,
                               acc[i][2] * scale, acc[i][3] * scale);
        *(float4*)&s[((size_t)bh * MEMN + i0 + ty * 4 + i) * TOTAL + j0 + tx * 4] = o;
    }
}

// ---------------- causal softmax over rows of S (query pos = MEM + i) -------
__global__ void __launch_bounds__(256) softmax_kernel(float* __restrict__ s)
{
    int bh = blockIdx.x >> 7;
    int i  = blockIdx.x & 127;
    float* row = s + ((size_t)bh * MEMN + i) * TOTAL;
    int tid = threadIdx.x;
    int limit = MEMN + i;           // valid keys j <= limit
    bool valid = (tid <= limit);
    float v = valid ? row[tid] : -3.4e38f;
    float m = block_max256(v);
    float e = valid ? expf(v - m) : 0.f;
    float sum = block_sum256(e);
    row[tid] = e / sum;
}

// ---------------- O = P@V, written straight into y chunk --------------------
// grid (it=2, bh=64), block 256: 64x128 output tile, 4x8 per thread
__global__ void __launch_bounds__(256) pv_kernel(
    const float* __restrict__ p, const float* __restrict__ v,
    float* __restrict__ y, int chunk)
{
    __shared__ float Ps[32][64];    // [j][i]
    __shared__ float Vs[32][128];   // [j][d]
    int bh = blockIdx.y;
    int i0 = blockIdx.x * 64;
    int b = bh >> 4, h = bh & 15;
    int tid = threadIdx.x, tx = tid & 15, ty = tid >> 4;
    const float* pb = p + (size_t)bh * MEMN * TOTAL;
    const float* vb = v + (size_t)bh * TOTAL * HD;
    float acc[4][8] = {};

    for (int j0 = 0; j0 < TOTAL; j0 += 32) {
        for (int t = tid; t < 64 * 8; t += 256) {
            int r = t >> 3;
            int c4 = (t & 7) * 4;
            float4 a = *(const float4*)&pb[(size_t)(i0 + r) * TOTAL + j0 + c4];
            Ps[c4 + 0][r] = a.x; Ps[c4 + 1][r] = a.y;
            Ps[c4 + 2][r] = a.z; Ps[c4 + 3][r] = a.w;
        }
        for (int t = tid; t < 32 * 32; t += 256) {
            int r = t >> 5;
            int c4 = (t & 31) * 4;
            *(float4*)&Vs[r][c4] = *(const float4*)&vb[(size_t)(j0 + r) * HD + c4];
        }
        __syncthreads();
        #pragma unroll
        for (int j = 0; j < 32; j++) {
            float4 a = *(const float4*)&Ps[j][ty * 4];
            float ar[4] = {a.x, a.y, a.z, a.w};
            float4 b0 = *(const float4*)&Vs[j][tx * 8];
            float4 b1 = *(const float4*)&Vs[j][tx * 8 + 4];
            float br[8] = {b0.x, b0.y, b0.z, b0.w, b1.x, b1.y, b1.z, b1.w};
            #pragma unroll
            for (int i = 0; i < 4; i++)
                #pragma unroll
                for (int jc = 0; jc < 8; jc++)
                    acc[i][jc] += ar[i] * br[jc];
        }
        __syncthreads();
    }
    #pragma unroll
    for (int i = 0; i < 4; i++) {
        size_t row = (size_t)b * SEQN + (size_t)chunk * MEMN + i0 + ty * 4 + i;
        float4 o0 = make_float4(acc[i][0], acc[i][1], acc[i][2], acc[i][3]);
        float4 o1 = make_float4(acc[i][4], acc[i][5], acc[i][6], acc[i][7]);
        *(float4*)&y[row * DIMN + h * HD + tx * 8]     = o0;
        *(float4*)&y[row * DIMN + h * HD + tx * 8 + 4] = o1;
    }
}

// ---------------- host orchestration ----------------------------------------
static void launch_gemm(const float* A, const float* B, float* C, int M, int N, int K)
{
    dim3 grid(N / GBN, M / GBM);
    gemm_tf32x3<<<grid, 256>>>(A, B, C, M, N, K);
}

extern "C" void kernel_launch(void* const* d_in, const int* in_sizes, int n_in,
                              void* d_out, int out_size)
{
    (void)in_sizes; (void)n_in; (void)out_size;
    const float* x   = (const float*)d_in[0];
    const float* fc  = (const float*)d_in[1];
    const float* fs  = (const float*)d_in[2];
    const float* om0 = (const float*)d_in[3];
    const float* wq  = (const float*)d_in[4];
    const float* wk  = (const float*)d_in[5];
    const float* wv  = (const float*)d_in[6];
    const float* wo  = (const float*)d_in[7];
    /* d_in[8] = wqm: unused (mq = mk and mq rows are never queried) */
    const float* wkm = (const float*)d_in[9];
    const float* wvm = (const float*)d_in[10];
    const float* wm  = (const float*)d_in[11];
    const float* ffw = (const float*)d_in[12];
    const float* w1  = (const float*)d_in[13];
    const float* w2  = (const float*)d_in[14];
    const float* w3  = (const float*)d_in[15];
    const float* mnw = (const float*)d_in[16];
    float* out = (float*)d_out;

    float *om, *sx, *om2, *h, *g1, *g3, *om4, *mk, *mv, *xq, *xk, *xv;
    float *q, *k, *v, *s, *y;
    cudaGetSymbolAddress((void**)&om,  g_om);
    cudaGetSymbolAddress((void**)&sx,  g_sx);
    cudaGetSymbolAddress((void**)&om2, g_om2);
    cudaGetSymbolAddress((void**)&h,   g_h);
    cudaGetSymbolAddress((void**)&g1,  g_g1);
    cudaGetSymbolAddress((void**)&g3,  g_g3);
    cudaGetSymbolAddress((void**)&om4, g_om4);
    cudaGetSymbolAddress((void**)&mk,  g_mk);
    cudaGetSymbolAddress((void**)&mv,  g_mv);
    cudaGetSymbolAddress((void**)&xq,  g_xq);
    cudaGetSymbolAddress((void**)&xk,  g_xk);
    cudaGetSymbolAddress((void**)&xv,  g_xv);
    cudaGetSymbolAddress((void**)&q,   g_q);
    cudaGetSymbolAddress((void**)&k,   g_k);
    cudaGetSymbolAddress((void**)&v,   g_v);
    cudaGetSymbolAddress((void**)&s,   g_s);
    cudaGetSymbolAddress((void**)&y,   g_y);

    const float scale = 0.08838834764831845f;   // 1/sqrt(128)

    for (int c = 0; c < NCHUNK; c++) {
        const float* omp;
        if (c == 0) {
            omp = om0;                           // origin_mem is contiguous [512][DIM]
        } else {
            gather_rows<<<RROWS, 256>>>(om, y, c - 1);
            omp = om;
        }
        gather_rows<<<RROWS, 256>>>(sx, x, c);

        // memory-stream FFN block
        launch_gemm(omp, wm, om2, RROWS, DIMN, DIMN);
        rmsnorm_kernel<<<RROWS, 256>>>(h, om2, ffw);
        launch_gemm(h, w1, g1, RROWS, HID, DIMN);
        launch_gemm(h, w3, g3, RROWS, HID, DIMN);
        silu_mul_kernel<<<(RROWS * HID / 4 + 255) / 256, 256>>>(g1, g3);
        launch_gemm(g1, w2, h, RROWS, DIMN, HID);          // f -> h (h dead now)
        add_rmsnorm_kernel<<<RROWS, 256>>>(om4, om2, h, mnw);

        // projections
        launch_gemm(om4, wkm, mk, RROWS, DIMN, DIMN);
        launch_gemm(om4, wvm, mv, RROWS, DIMN, DIMN);
        launch_gemm(sx,  wq,  xq, RROWS, DIMN, DIMN);
        launch_gemm(sx,  wk,  xk, RROWS, DIMN, DIMN);
        launch_gemm(sx,  wv,  xv, RROWS, DIMN, DIMN);

        // assemble roped q/k/v
        build_kv_kernel<<<(BATCH * TOTAL * NH * 64 + 255) / 256, 256>>>(
            mk, mv, xk, xv, fc, fs, k, v);
        build_q_kernel<<<(BATCH * MEMN * NH * 64 + 255) / 256, 256>>>(xq, fc, fs, q);

        // attention (only output rows MEM..2*MEM-1 are needed)
        {
            dim3 g(4, 2, BATCH * NH);
            qk_kernel<<<g, 256>>>(q, k, s, scale);
        }
        softmax_kernel<<<BATCH * NH * MEMN, 256>>>(s);
        {
            dim3 g(2, BATCH * NH);
            pv_kernel<<<g, 256>>>(s, v, y, c);
        }
    }

    // final projection: out = y @ wo
    launch_gemm(y, wo, out, BATCH * SEQN, DIMN, DIMN);
}

// round 8
// speedup vs baseline: 1.2477x; 1.0435x over previous
#include <cuda_runtime.h>
#include <math.h>

#define DIMN 2048
#define NH 16
#define HD 128
#define MEMN 128
#define SEQN 2048
#define BATCH 4
#define HID 5632
#define NCHUNK (SEQN / MEMN)     // 16
#define RROWS (BATCH * MEMN)     // 512 rows per step
#define TOTAL (2 * MEMN)         // 256
#define EPS 1e-5f

// ---------------- scratch (__device__ globals; no allocation) ----------------
__device__ float g_om [RROWS * DIMN];
__device__ float g_sx [RROWS * DIMN];
__device__ float g_om2[RROWS * DIMN];
__device__ float g_h  [RROWS * DIMN];   // reused for FFN output f
__device__ float g_g1 [RROWS * HID];
__device__ float g_g3 [RROWS * HID];
__device__ float g_om4[RROWS * DIMN];
__device__ float g_mk [RROWS * DIMN];
__device__ float g_mv [RROWS * DIMN];
__device__ float g_xq [RROWS * DIMN];
__device__ float g_xk [RROWS * DIMN];
__device__ float g_xv [RROWS * DIMN];
__device__ float g_q  [BATCH * NH * MEMN  * HD];   // roped queries (x part only)
__device__ float g_k  [BATCH * NH * TOTAL * HD];
__device__ float g_v  [BATCH * NH * TOTAL * HD];
__device__ float g_s  [BATCH * NH * MEMN * TOTAL]; // scores / probs
__device__ float g_y  [BATCH * SEQN * DIMN];       // per-chunk outputs == om chain

// ---------------- reductions ----------------
__device__ __forceinline__ float block_sum256(float v) {
    __shared__ float sh[8];
    #pragma unroll
    for (int o = 16; o > 0; o >>= 1) v += __shfl_xor_sync(0xffffffffu, v, o);
    if ((threadIdx.x & 31) == 0) sh[threadIdx.x >> 5] = v;
    __syncthreads();
    float t = 0.f;
    if (threadIdx.x < 32) {
        t = (threadIdx.x < 8) ? sh[threadIdx.x] : 0.f;
        #pragma unroll
        for (int o = 4; o > 0; o >>= 1) t += __shfl_xor_sync(0xffffffffu, t, o);
        if (threadIdx.x == 0) sh[0] = t;
    }
    __syncthreads();
    float r = sh[0];
    __syncthreads();
    return r;
}

__device__ __forceinline__ float block_max256(float v) {
    __shared__ float sh[8];
    #pragma unroll
    for (int o = 16; o > 0; o >>= 1) v = fmaxf(v, __shfl_xor_sync(0xffffffffu, v, o));
    if ((threadIdx.x & 31) == 0) sh[threadIdx.x >> 5] = v;
    __syncthreads();
    float t = -3.4e38f;
    if (threadIdx.x < 32) {
        t = (threadIdx.x < 8) ? sh[threadIdx.x] : -3.4e38f;
        #pragma unroll
        for (int o = 4; o > 0; o >>= 1) t = fmaxf(t, __shfl_xor_sync(0xffffffffu, t, o));
        if (threadIdx.x == 0) sh[0] = t;
    }
    __syncthreads();
    float r = sh[0];
    __syncthreads();
    return r;
}

// ---------------- tf32 helpers ----------------
__device__ __forceinline__ unsigned f2tf32(float f) {
    unsigned u;
    asm("cvt.rna.tf32.f32 %0, %1;" : "=r"(u) : "f"(f));
    return u;
}

// split f into hi (tf32) and lo (tf32 of residual)
__device__ __forceinline__ void split_tf32(float f, unsigned& hi, unsigned& lo) {
    hi = f2tf32(f);
    lo = f2tf32(f - __uint_as_float(hi));
}

__device__ __forceinline__ void mma_tf32(float c[4], const unsigned a[4], const unsigned b[2]) {
    asm volatile(
        "mma.sync.aligned.m16n8k8.row.col.f32.tf32.tf32.f32 "
        "{%0,%1,%2,%3}, {%4,%5,%6,%7}, {%8,%9}, {%0,%1,%2,%3};"
        : "+f"(c[0]), "+f"(c[1]), "+f"(c[2]), "+f"(c[3])
        : "r"(a[0]), "r"(a[1]), "r"(a[2]), "r"(a[3]), "r"(b[0]), "r"(b[1]));
}

// ---------------- 3xTF32 tensor-core GEMM: C = A @ B, row-major -------------
// BM=64, BN=128, BK=32, 256 threads (8 warps, 32x32 warp tiles).
// Register-prefetch double buffering (unchanged from R7).
// NEW (R8): H/L interleaved in smem -> every fragment load is one LDS.64
// fetching the (hi,lo) pair; B gains an n-swizzle killing its 4-way bank
// conflict. Per-warp frag LDS per K-iter: 128 scalar -> 64 LDS.64, all
// conflict-free. MMA order per k unchanged -> rel_err bit-identical.
// Static smem = 64*32*2*4 + 32*128*2*4 = 49152 B exactly (static cap).
#define GBM 64
#define GBN 128
#define GBK 32

__global__ void __launch_bounds__(256) gemm_tf32x3(
    const float* __restrict__ A, const float* __restrict__ B,
    float* __restrict__ C, int M, int N, int K)
{
    __shared__ unsigned AsHL[GBM][GBK][2];   // [m][k][hi/lo], k XOR-swizzled by (m&7)*4
    __shared__ unsigned BsHL[GBK][GBN][2];   // [k][n][hi/lo], n XOR-swizzled by (k&3)*8

    const int tid  = threadIdx.x;
    const int lane = tid & 31;
    const int wid  = tid >> 5;
    const int warp_m = wid & 1;        // 2 warps along M
    const int warp_n = wid >> 1;       // 4 warps along N
    const int row0 = blockIdx.y * GBM;
    const int col0 = blockIdx.x * GBN;

    float4 ra[2];    // A tile 64x32 floats: 2 float4/thread
    float4 rb[4];    // B tile 32x128 floats: 4 float4/thread

    float acc[2][4][4];
    #pragma unroll
    for (int i = 0; i < 2; i++)
        #pragma unroll
        for (int j = 0; j < 4; j++)
            #pragma unroll
            for (int l = 0; l < 4; l++) acc[i][j][l] = 0.f;

    // ---- prologue: load tile 0 into registers ----
    #pragma unroll
    for (int i = 0; i < 2; i++) {
        int idx = tid + i * 256;
        int m = idx >> 3, k4 = idx & 7;
        ra[i] = *(const float4*)&A[(size_t)(row0 + m) * K + k4 * 4];
    }
    #pragma unroll
    for (int i = 0; i < 4; i++) {
        int idx = tid + i * 256;
        int kr = idx >> 5, n4 = idx & 31;
        rb[i] = *(const float4*)&B[(size_t)kr * N + col0 + n4 * 4];
    }

    for (int kk = 0; kk < K; kk += GBK) {
        // split + store the tile we just loaded into registers (H/L interleaved)
        #pragma unroll
        for (int i = 0; i < 2; i++) {
            int idx = tid + i * 256;
            int m = idx >> 3, k4 = idx & 7;
            int kc = (k4 * 4) ^ ((m & 7) * 4);    // XOR swizzle (4-aligned group stays contiguous)
            unsigned h0, l0, h1, l1, h2, l2, h3, l3;
            split_tf32(ra[i].x, h0, l0);
            split_tf32(ra[i].y, h1, l1);
            split_tf32(ra[i].z, h2, l2);
            split_tf32(ra[i].w, h3, l3);
            *(uint4*)&AsHL[m][kc][0]     = make_uint4(h0, l0, h1, l1);
            *(uint4*)&AsHL[m][kc + 2][0] = make_uint4(h2, l2, h3, l3);
        }
        #pragma unroll
        for (int i = 0; i < 4; i++) {
            int idx = tid + i * 256;
            int kr = idx >> 5, n4 = idx & 31;
            int nc = (n4 * 4) ^ ((kr & 3) * 8);   // XOR swizzle (8-step; 4-group stays contiguous)
            unsigned h0, l0, h1, l1, h2, l2, h3, l3;
            split_tf32(rb[i].x, h0, l0);
            split_tf32(rb[i].y, h1, l1);
            split_tf32(rb[i].z, h2, l2);
            split_tf32(rb[i].w, h3, l3);
            *(uint4*)&BsHL[kr][nc][0]     = make_uint4(h0, l0, h1, l1);
            *(uint4*)&BsHL[kr][nc + 2][0] = make_uint4(h2, l2, h3, l3);
        }
        __syncthreads();

        // prefetch next tile into registers (LDGs issue now, waited at next store)
        const bool more = (kk + GBK < K);
        if (more) {
            #pragma unroll
            for (int i = 0; i < 2; i++) {
                int idx = tid + i * 256;
                int m = idx >> 3, k4 = idx & 7;
                ra[i] = *(const float4*)&A[(size_t)(row0 + m) * K + kk + GBK + k4 * 4];
            }
            #pragma unroll
            for (int i = 0; i < 4; i++) {
                int idx = tid + i * 256;
                int kr = idx >> 5, n4 = idx & 31;
                rb[i] = *(const float4*)&B[(size_t)(kk + GBK + kr) * N + col0 + n4 * 4];
            }
        }

        // ---- compute: 4 k-slices x 24 MMAs ----
        #pragma unroll
        for (int ks = 0; ks < 4; ks++) {
            int kq = ks * 8 + (lane & 3);
            int swb = (lane & 3) * 8;             // == (kq&3)*8, same for kq+4
            unsigned afH[2][4], afL[2][4];
            unsigned bfH[4][2], bfL[4][2];
            #pragma unroll
            for (int mf = 0; mf < 2; mf++) {
                int m  = warp_m * 32 + mf * 16 + (lane >> 2);
                int sw = (lane >> 2) * 4;          // == (m&7)*4, same for m+8
                uint2 a0 = *(const uint2*)&AsHL[m][kq ^ sw][0];
                uint2 a1 = *(const uint2*)&AsHL[m + 8][kq ^ sw][0];
                uint2 a2 = *(const uint2*)&AsHL[m][(kq + 4) ^ sw][0];
                uint2 a3 = *(const uint2*)&AsHL[m + 8][(kq + 4) ^ sw][0];
                afH[mf][0] = a0.x; afL[mf][0] = a0.y;
                afH[mf][1] = a1.x; afL[mf][1] = a1.y;
                afH[mf][2] = a2.x; afL[mf][2] = a2.y;
                afH[mf][3] = a3.x; afL[mf][3] = a3.y;
            }
            #pragma unroll
            for (int nf = 0; nf < 4; nf++) {
                int n = warp_n * 32 + nf * 8 + (lane >> 2);
                uint2 b0 = *(const uint2*)&BsHL[kq][n ^ swb][0];
                uint2 b1 = *(const uint2*)&BsHL[kq + 4][n ^ swb][0];
                bfH[nf][0] = b0.x; bfL[nf][0] = b0.y;
                bfH[nf][1] = b1.x; bfL[nf][1] = b1.y;
            }
            #pragma unroll
            for (int mf = 0; mf < 2; mf++)
                #pragma unroll
                for (int nf = 0; nf < 4; nf++) {
                    mma_tf32(acc[mf][nf], afL[mf], bfH[nf]);  // Al*Bh
                    mma_tf32(acc[mf][nf], afH[mf], bfL[nf]);  // Ah*Bl
                    mma_tf32(acc[mf][nf], afH[mf], bfH[nf]);  // Ah*Bh (largest last)
                }
        }
        __syncthreads();   // done reading smem; next iter overwrites
    }

    // epilogue
    #pragma unroll
    for (int mf = 0; mf < 2; mf++) {
        int row = row0 + warp_m * 32 + mf * 16 + (lane >> 2);
        #pragma unroll
        for (int nf = 0; nf < 4; nf++) {
            int col = col0 + warp_n * 32 + nf * 8 + 2 * (lane & 3);
            *(float2*)&C[(size_t)row * N + col] =
                make_float2(acc[mf][nf][0], acc[mf][nf][1]);
            *(float2*)&C[(size_t)(row + 8) * N + col] =
                make_float2(acc[mf][nf][2], acc[mf][nf][3]);
        }
    }
}

// ---------------- gather rows of a [B][SEQ][DIM] tensor chunk into [512][DIM]
__global__ void __launch_bounds__(256) gather_rows(
    float* __restrict__ dst, const float* __restrict__ src, int chunk)
{
    int row = blockIdx.x;                // 0..511
    int b = row >> 7, i = row & 127;
    const float4* s = (const float4*)&src[((size_t)b * SEQN + chunk * MEMN + i) * DIMN];
    float4* d = (float4*)&dst[(size_t)row * DIMN];
    #pragma unroll
    for (int t = 0; t < 2; t++) d[threadIdx.x + t * 256] = s[threadIdx.x + t * 256];
}

// ---------------- rmsnorm: out = in * rsqrt(mean(in^2)+eps) * w --------------
__global__ void __launch_bounds__(256) rmsnorm_kernel(
    float* __restrict__ out, const float* __restrict__ in, const float* __restrict__ w)
{
    int row = blockIdx.x;
    const float* xr = in + (size_t)row * DIMN;
    float vals[8];
    float ss = 0.f;
    #pragma unroll
    for (int t = 0; t < 8; t++) {
        float v = xr[threadIdx.x + t * 256];
        vals[t] = v; ss += v * v;
    }
    float tot = block_sum256(ss);
    float sc = rsqrtf(tot * (1.0f / DIMN) + EPS);
    #pragma unroll
    for (int t = 0; t < 8; t++)
        out[(size_t)row * DIMN + threadIdx.x + t * 256] =
            vals[t] * sc * w[threadIdx.x + t * 256];
}

// ---------------- out = rmsnorm(a + b) * w ----------------------------------
__global__ void __launch_bounds__(256) add_rmsnorm_kernel(
    float* __restrict__ out, const float* __restrict__ a,
    const float* __restrict__ b, const float* __restrict__ w)
{
    int row = blockIdx.x;
    const float* ar = a + (size_t)row * DIMN;
    const float* br = b + (size_t)row * DIMN;
    float vals[8];
    float ss = 0.f;
    #pragma unroll
    for (int t = 0; t < 8; t++) {
        float v = ar[threadIdx.x + t * 256] + br[threadIdx.x + t * 256];
        vals[t] = v; ss += v * v;
    }
    float tot = block_sum256(ss);
    float sc = rsqrtf(tot * (1.0f / DIMN) + EPS);
    #pragma unroll
    for (int t = 0; t < 8; t++)
        out[(size_t)row * DIMN + threadIdx.x + t * 256] =
            vals[t] * sc * w[threadIdx.x + t * 256];
}

// ---------------- g1 = silu(g1) * g3 (float4 elementwise) -------------------
__global__ void __launch_bounds__(256) silu_mul_kernel(
    float* __restrict__ a, const float* __restrict__ b)
{
    int idx = blockIdx.x * 256 + threadIdx.x;
    int n4 = RROWS * HID / 4;
    if (idx >= n4) return;
    float4 av = ((float4*)a)[idx];
    float4 bv = ((const float4*)b)[idx];
    av.x = av.x / (1.f + expf(-av.x)) * bv.x;
    av.y = av.y / (1.f + expf(-av.y)) * bv.y;
    av.z = av.z / (1.f + expf(-av.z)) * bv.z;
    av.w = av.w / (1.f + expf(-av.w)) * bv.w;
    ((float4*)a)[idx] = av;
}

// ---------------- build K,V (all 256 positions) with RoPE on K --------------
__global__ void __launch_bounds__(256) build_kv_kernel(
    const float* __restrict__ mk, const float* __restrict__ mv,
    const float* __restrict__ xk, const float* __restrict__ xv,
    const float* __restrict__ fc, const float* __restrict__ fs,
    float* __restrict__ k, float* __restrict__ v)
{
    int idx = blockIdx.x * 256 + threadIdx.x;   // B*TOTAL*NH*64 = 1048576
    if (idx >= BATCH * TOTAL * NH * (HD / 2)) return;
    int j   = idx & 63;
    int h   = (idx >> 6) & 15;
    int pos = (idx >> 10) & 255;
    int b   = idx >> 18;
    int col = h * HD + 2 * j;
    const float *sk, *sv;
    if (pos < MEMN) {
        size_t r = (size_t)(b * MEMN + pos) * DIMN + col;
        sk = mk + r; sv = mv + r;
    } else {
        size_t r = (size_t)(b * MEMN + pos - MEMN) * DIMN + col;
        sk = xk + r; sv = xv + r;
    }
    float c = fc[pos * 64 + j], s = fs[pos * 64 + j];
    float kr = sk[0], ki = sk[1];
    size_t o = ((size_t)(b * NH + h) * TOTAL + pos) * HD + 2 * j;
    k[o]     = kr * c - ki * s;
    k[o + 1] = kr * s + ki * c;
    v[o]     = sv[0];
    v[o + 1] = sv[1];
}

// ---------------- build Q (only x part, positions 128..255) with RoPE -------
__global__ void __launch_bounds__(256) build_q_kernel(
    const float* __restrict__ xq, const float* __restrict__ fc,
    const float* __restrict__ fs, float* __restrict__ q)
{
    int idx = blockIdx.x * 256 + threadIdx.x;   // B*MEM*NH*64 = 524288
    if (idx >= BATCH * MEMN * NH * (HD / 2)) return;
    int j = idx & 63;
    int h = (idx >> 6) & 15;
    int i = (idx >> 10) & 127;
    int b = idx >> 17;
    int pos = MEMN + i;
    const float* src = xq + (size_t)(b * MEMN + i) * DIMN + h * HD + 2 * j;
    float c = fc[pos * 64 + j], s = fs[pos * 64 + j];
    float r = src[0], im = src[1];
    size_t o = ((size_t)(b * NH + h) * MEMN + i) * HD + 2 * j;
    q[o]     = r * c - im * s;
    q[o + 1] = r * s + im * c;
}

// ---------------- S[bh][i][j] = scale * q[bh][i]·k[bh][j] -------------------
// grid (jt=4, it=2, bh=64), block 256
__global__ void __launch_bounds__(256) qk_kernel(
    const float* __restrict__ q, const float* __restrict__ k,
    float* __restrict__ s, float scale)
{
    __shared__ float Qs[64][64];   // [d][i]
    __shared__ float Ks[64][64];   // [d][j]
    int bh = blockIdx.z;
    int i0 = blockIdx.y * 64;
    int j0 = blockIdx.x * 64;
    int tid = threadIdx.x, tx = tid & 15, ty = tid >> 4;
    const float* qb = q + (size_t)bh * MEMN * HD;
    const float* kb = k + (size_t)bh * TOTAL * HD;
    float acc[4][4] = {};

    for (int dc = 0; dc < HD; dc += 64) {
        for (int t = tid; t < 64 * 16; t += 256) {
            int r = t >> 4;
            int c4 = (t & 15) * 4;
            float4 a = *(const float4*)&qb[(size_t)(i0 + r) * HD + dc + c4];
            Qs[c4 + 0][r] = a.x; Qs[c4 + 1][r] = a.y;
            Qs[c4 + 2][r] = a.z; Qs[c4 + 3][r] = a.w;
            float4 b = *(const float4*)&kb[(size_t)(j0 + r) * HD + dc + c4];
            Ks[c4 + 0][r] = b.x; Ks[c4 + 1][r] = b.y;
            Ks[c4 + 2][r] = b.z; Ks[c4 + 3][r] = b.w;
        }
        __syncthreads();
        #pragma unroll
        for (int d = 0; d < 64; d++) {
            float4 a = *(const float4*)&Qs[d][ty * 4];
            float4 b = *(const float4*)&Ks[d][tx * 4];
            float ar[4] = {a.x, a.y, a.z, a.w};
            float br[4] = {b.x, b.y, b.z, b.w};
            #pragma unroll
            for (int i = 0; i < 4; i++)
                #pragma unroll
                for (int j = 0; j < 4; j++)
                    acc[i][j] += ar[i] * br[j];
        }
        __syncthreads();
    }
    #pragma unroll
    for (int i = 0; i < 4; i++) {
        float4 o = make_float4(acc[i][0] * scale, acc[i][1] * scale,
                               acc[i][2] * scale, acc[i][3] * scale);
        *(float4*)&s[((size_t)bh * MEMN + i0 + ty * 4 + i) * TOTAL + j0 + tx * 4] = o;
    }
}

// ---------------- causal softmax over rows of S (query pos = MEM + i) -------
__global__ void __launch_bounds__(256) softmax_kernel(float* __restrict__ s)
{
    int bh = blockIdx.x >> 7;
    int i  = blockIdx.x & 127;
    float* row = s + ((size_t)bh * MEMN + i) * TOTAL;
    int tid = threadIdx.x;
    int limit = MEMN + i;           // valid keys j <= limit
    bool valid = (tid <= limit);
    float v = valid ? row[tid] : -3.4e38f;
    float m = block_max256(v);
    float e = valid ? expf(v - m) : 0.f;
    float sum = block_sum256(e);
    row[tid] = e / sum;
}

// ---------------- O = P@V, written straight into y chunk --------------------
// grid (it=2, bh=64), block 256: 64x128 output tile, 4x8 per thread
__global__ void __launch_bounds__(256) pv_kernel(
    const float* __restrict__ p, const float* __restrict__ v,
    float* __restrict__ y, int chunk)
{
    __shared__ float Ps[32][64];    // [j][i]
    __shared__ float Vs[32][128];   // [j][d]
    int bh = blockIdx.y;
    int i0 = blockIdx.x * 64;
    int b = bh >> 4, h = bh & 15;
    int tid = threadIdx.x, tx = tid & 15, ty = tid >> 4;
    const float* pb = p + (size_t)bh * MEMN * TOTAL;
    const float* vb = v + (size_t)bh * TOTAL * HD;
    float acc[4][8] = {};

    for (int j0 = 0; j0 < TOTAL; j0 += 32) {
        for (int t = tid; t < 64 * 8; t += 256) {
            int r = t >> 3;
            int c4 = (t & 7) * 4;
            float4 a = *(const float4*)&pb[(size_t)(i0 + r) * TOTAL + j0 + c4];
            Ps[c4 + 0][r] = a.x; Ps[c4 + 1][r] = a.y;
            Ps[c4 + 2][r] = a.z; Ps[c4 + 3][r] = a.w;
        }
        for (int t = tid; t < 32 * 32; t += 256) {
            int r = t >> 5;
            int c4 = (t & 31) * 4;
            *(float4*)&Vs[r][c4] = *(const float4*)&vb[(size_t)(j0 + r) * HD + c4];
        }
        __syncthreads();
        #pragma unroll
        for (int j = 0; j < 32; j++) {
            float4 a = *(const float4*)&Ps[j][ty * 4];
            float ar[4] = {a.x, a.y, a.z, a.w};
            float4 b0 = *(const float4*)&Vs[j][tx * 8];
            float4 b1 = *(const float4*)&Vs[j][tx * 8 + 4];
            float br[8] = {b0.x, b0.y, b0.z, b0.w, b1.x, b1.y, b1.z, b1.w};
            #pragma unroll
            for (int i = 0; i < 4; i++)
                #pragma unroll
                for (int jc = 0; jc < 8; jc++)
                    acc[i][jc] += ar[i] * br[jc];
        }
        __syncthreads();
    }
    #pragma unroll
    for (int i = 0; i < 4; i++) {
        size_t row = (size_t)b * SEQN + (size_t)chunk * MEMN + i0 + ty * 4 + i;
        float4 o0 = make_float4(acc[i][0], acc[i][1], acc[i][2], acc[i][3]);
        float4 o1 = make_float4(acc[i][4], acc[i][5], acc[i][6], acc[i][7]);
        *(float4*)&y[row * DIMN + h * HD + tx * 8]     = o0;
        *(float4*)&y[row * DIMN + h * HD + tx * 8 + 4] = o1;
    }
}

// ---------------- host orchestration ----------------------------------------
static void launch_gemm(const float* A, const float* B, float* C, int M, int N, int K)
{
    dim3 grid(N / GBN, M / GBM);
    gemm_tf32x3<<<grid, 256>>>(A, B, C, M, N, K);
}

extern "C" void kernel_launch(void* const* d_in, const int* in_sizes, int n_in,
                              void* d_out, int out_size)
{
    (void)in_sizes; (void)n_in; (void)out_size;
    const float* x   = (const float*)d_in[0];
    const float* fc  = (const float*)d_in[1];
    const float* fs  = (const float*)d_in[2];
    const float* om0 = (const float*)d_in[3];
    const float* wq  = (const float*)d_in[4];
    const float* wk  = (const float*)d_in[5];
    const float* wv  = (const float*)d_in[6];
    const float* wo  = (const float*)d_in[7];
    /* d_in[8] = wqm: unused (mq = mk and mq rows are never queried) */
    const float* wkm = (const float*)d_in[9];
    const float* wvm = (const float*)d_in[10];
    const float* wm  = (const float*)d_in[11];
    const float* ffw = (const float*)d_in[12];
    const float* w1  = (const float*)d_in[13];
    const float* w2  = (const float*)d_in[14];
    const float* w3  = (const float*)d_in[15];
    const float* mnw = (const float*)d_in[16];
    float* out = (float*)d_out;

    float *om, *sx, *om2, *h, *g1, *g3, *om4, *mk, *mv, *xq, *xk, *xv;
    float *q, *k, *v, *s, *y;
    cudaGetSymbolAddress((void**)&om,  g_om);
    cudaGetSymbolAddress((void**)&sx,  g_sx);
    cudaGetSymbolAddress((void**)&om2, g_om2);
    cudaGetSymbolAddress((void**)&h,   g_h);
    cudaGetSymbolAddress((void**)&g1,  g_g1);
    cudaGetSymbolAddress((void**)&g3,  g_g3);
    cudaGetSymbolAddress((void**)&om4, g_om4);
    cudaGetSymbolAddress((void**)&mk,  g_mk);
    cudaGetSymbolAddress((void**)&mv,  g_mv);
    cudaGetSymbolAddress((void**)&xq,  g_xq);
    cudaGetSymbolAddress((void**)&xk,  g_xk);
    cudaGetSymbolAddress((void**)&xv,  g_xv);
    cudaGetSymbolAddress((void**)&q,   g_q);
    cudaGetSymbolAddress((void**)&k,   g_k);
    cudaGetSymbolAddress((void**)&v,   g_v);
    cudaGetSymbolAddress((void**)&s,   g_s);
    cudaGetSymbolAddress((void**)&y,   g_y);

    const float scale = 0.08838834764831845f;   // 1/sqrt(128)

    for (int c = 0; c < NCHUNK; c++) {
        const float* omp;
        if (c == 0) {
            omp = om0;                           // origin_mem is contiguous [512][DIM]
        } else {
            gather_rows<<<RROWS, 256>>>(om, y, c - 1);
            omp = om;
        }
        gather_rows<<<RROWS, 256>>>(sx, x, c);

        // memory-stream FFN block
        launch_gemm(omp, wm, om2, RROWS, DIMN, DIMN);
        rmsnorm_kernel<<<RROWS, 256>>>(h, om2, ffw);
        launch_gemm(h, w1, g1, RROWS, HID, DIMN);
        launch_gemm(h, w3, g3, RROWS, HID, DIMN);
        silu_mul_kernel<<<(RROWS * HID / 4 + 255) / 256, 256>>>(g1, g3);
        launch_gemm(g1, w2, h, RROWS, DIMN, HID);          // f -> h (h dead now)
        add_rmsnorm_kernel<<<RROWS, 256>>>(om4, om2, h, mnw);

        // projections
        launch_gemm(om4, wkm, mk, RROWS, DIMN, DIMN);
        launch_gemm(om4, wvm, mv, RROWS, DIMN, DIMN);
        launch_gemm(sx,  wq,  xq, RROWS, DIMN, DIMN);
        launch_gemm(sx,  wk,  xk, RROWS, DIMN, DIMN);
        launch_gemm(sx,  wv,  xv, RROWS, DIMN, DIMN);

        // assemble roped q/k/v
        build_kv_kernel<<<(BATCH * TOTAL * NH * 64 + 255) / 256, 256>>>(
            mk, mv, xk, xv, fc, fs, k, v);
        build_q_kernel<<<(BATCH * MEMN * NH * 64 + 255) / 256, 256>>>(xq, fc, fs, q);

        // attention (only output rows MEM..2*MEM-1 are needed)
        {
            dim3 g(4, 2, BATCH * NH);
            qk_kernel<<<g, 256>>>(q, k, s, scale);
        }
        softmax_kernel<<<BATCH * NH * MEMN, 256>>>(s);
        {
            dim3 g(2, BATCH * NH);
            pv_kernel<<<g, 256>>>(s, v, y, c);
        }
    }

    // final projection: out = y @ wo
    launch_gemm(y, wo, out, BATCH * SEQN, DIMN, DIMN);
}